// round 3
// baseline (speedup 1.0000x reference)
#include <cuda_runtime.h>
#include <math.h>

#define BB 4
#define NN 2048
#define DD 512
#define HH 8
#define RR (BB*NN)   // 8192 rows
#define EE 2048      // proj width

// ---------------- scratch (static device globals; no allocation) -------------
__device__ float g_norm[(size_t)RR*DD];   // 16 MB  LN(x)
__device__ float g_proj[(size_t)RR*EE];   // 64 MB  silu(normX @ uvqk) = [u|v|q|k]
__device__ float g_attn[(size_t)RR*DD];   // 16 MB  attention output (H*dL=512)
__device__ float g_oin [(size_t)RR*DD];   // 16 MB  u * LN(attn)

__device__ __forceinline__ float silu_f(float v) { return v / (1.0f + expf(-v)); }

// ---------------- LayerNorm of x -> g_norm  (1 block / row, 128 thr) ---------
__global__ void ln_x_kernel(const float* __restrict__ x) {
    int row = blockIdx.x;
    int t = threadIdx.x;
    float4 v = ((const float4*)(x + (size_t)row * DD))[t];
    float s  = v.x + v.y + v.z + v.w;
    float ss = v.x*v.x + v.y*v.y + v.z*v.z + v.w*v.w;
    #pragma unroll
    for (int o = 16; o; o >>= 1) {
        s  += __shfl_xor_sync(0xffffffffu, s,  o);
        ss += __shfl_xor_sync(0xffffffffu, ss, o);
    }
    __shared__ float shs[4], shq[4];
    if ((t & 31) == 0) { shs[t >> 5] = s; shq[t >> 5] = ss; }
    __syncthreads();
    s  = shs[0] + shs[1] + shs[2] + shs[3];
    ss = shq[0] + shq[1] + shq[2] + shq[3];
    float mu  = s * (1.0f / DD);
    float var = ss * (1.0f / DD) - mu * mu;
    float rs  = rsqrtf(var + 1e-6f);
    float4 o;
    o.x = (v.x - mu) * rs; o.y = (v.y - mu) * rs;
    o.z = (v.z - mu) * rs; o.w = (v.w - mu) * rs;
    ((float4*)(g_norm + (size_t)row * DD))[t] = o;
}

// ---------------- GEMM1: g_proj = silu(g_norm[8192x512] @ uvqk[512x2048]) ----
__global__ __launch_bounds__(256) void gemm_proj_kernel(const float* __restrict__ W) {
    __shared__ float As[16][128];
    __shared__ float Bs[16][128];
    int bn = blockIdx.x * 128, bm = blockIdx.y * 128;
    int tid = threadIdx.x, tx = tid & 15, ty = tid >> 4;
    float acc[8][8] = {};
    for (int k0 = 0; k0 < DD; k0 += 16) {
        #pragma unroll
        for (int i = 0; i < 2; i++) {
            int idx = tid * 2 + i;                 // 0..511
            int r = idx >> 2, c = idx & 3;         // A: 128 rows x 4 float4
            float4 a = *(const float4*)(g_norm + (size_t)(bm + r) * DD + k0 + c * 4);
            As[c*4+0][r] = a.x; As[c*4+1][r] = a.y;
            As[c*4+2][r] = a.z; As[c*4+3][r] = a.w;
            int rb = idx >> 5, cb = idx & 31;      // B: 16 rows x 32 float4
            *(float4*)(&Bs[rb][cb*4]) =
                *(const float4*)(W + (size_t)(k0 + rb) * EE + bn + cb * 4);
        }
        __syncthreads();
        #pragma unroll
        for (int k = 0; k < 16; k++) {
            float a[8], b[8];
            *(float4*)(a)     = *(const float4*)(&As[k][ty*8]);
            *(float4*)(a + 4) = *(const float4*)(&As[k][ty*8 + 4]);
            *(float4*)(b)     = *(const float4*)(&Bs[k][tx*8]);
            *(float4*)(b + 4) = *(const float4*)(&Bs[k][tx*8 + 4]);
            #pragma unroll
            for (int i = 0; i < 8; i++)
                #pragma unroll
                for (int j = 0; j < 8; j++) acc[i][j] += a[i] * b[j];
        }
        __syncthreads();
    }
    #pragma unroll
    for (int i = 0; i < 8; i++) {
        float4 o0, o1;
        o0.x = silu_f(acc[i][0]); o0.y = silu_f(acc[i][1]);
        o0.z = silu_f(acc[i][2]); o0.w = silu_f(acc[i][3]);
        o1.x = silu_f(acc[i][4]); o1.y = silu_f(acc[i][5]);
        o1.z = silu_f(acc[i][6]); o1.w = silu_f(acc[i][7]);
        float* cp = g_proj + (size_t)(bm + ty*8 + i) * EE + bn + tx*8;
        *(float4*)cp = o0; *(float4*)(cp + 4) = o1;
    }
}

// ---------------- HSTU attention -------------------------------------------
// per (b, h, 64-query block): O = sum_m (silu(QK^T)/N * causal) V
// smem: Qt[d][i], Kt[d][m] transposed (ld 68) -> conflict-free LDS.128 operands
#define ALD 68
#define ATT_SMEM_BYTES (4 * 64 * ALD * (int)sizeof(float))
extern __shared__ float smem_att[];

__global__ __launch_bounds__(256) void attn_kernel() {
    float* Qt = smem_att;                 // [64][ALD]  Qt[d*ALD + i]
    float* Kt = Qt + 64 * ALD;            // Kt[d*ALD + m]
    float* Vs = Kt + 64 * ALD;            // Vs[m*ALD + d]
    float* Ss = Vs + 64 * ALD;            // Ss[i*ALD + m]
    int qb = (int)(gridDim.x - 1 - blockIdx.x);   // big blocks first (causal balance)
    int h = blockIdx.y, b = blockIdx.z;
    int tid = threadIdx.x, tx = tid & 15, ty = tid >> 4;
    const float* base = g_proj + (size_t)b * NN * EE;
    const float* Qg = base + 1024 + h * 64;  // q at cols [1024,1536)
    const float* Kg = base + 1536 + h * 64;  // k at cols [1536,2048)
    const float* Vg = base + 512  + h * 64;  // v at cols [512,1024)
    int q0 = qb * 64;

    // load Q block transposed
    #pragma unroll
    for (int t = 0; t < 4; t++) {
        int idx = tid + t * 256;
        int r = idx >> 4, c = idx & 15;
        float4 q = *(const float4*)(Qg + (size_t)(q0 + r) * EE + c * 4);
        Qt[(c*4+0)*ALD + r] = q.x; Qt[(c*4+1)*ALD + r] = q.y;
        Qt[(c*4+2)*ALD + r] = q.z; Qt[(c*4+3)*ALD + r] = q.w;
    }

    float acc[4][4] = {};
    for (int mb = 0; mb <= qb; mb++) {
        int m0 = mb * 64;
        #pragma unroll
        for (int t = 0; t < 4; t++) {
            int idx = tid + t * 256;
            int r = idx >> 4, c = idx & 15;
            float4 kq = *(const float4*)(Kg + (size_t)(m0 + r) * EE + c * 4);
            Kt[(c*4+0)*ALD + r] = kq.x; Kt[(c*4+1)*ALD + r] = kq.y;
            Kt[(c*4+2)*ALD + r] = kq.z; Kt[(c*4+3)*ALD + r] = kq.w;
            float4 vq = *(const float4*)(Vg + (size_t)(m0 + r) * EE + c * 4);
            *(float4*)(&Vs[r*ALD + c*4]) = vq;
        }
        __syncthreads();

        // S = Q K^T  (each thread: 4 rows x 4 cols)
        float s[4][4] = {};
        #pragma unroll 8
        for (int d = 0; d < 64; d++) {
            float4 qv = *(const float4*)(&Qt[d*ALD + ty*4]);
            float4 kv = *(const float4*)(&Kt[d*ALD + tx*4]);
            float qa[4] = {qv.x, qv.y, qv.z, qv.w};
            float ka[4] = {kv.x, kv.y, kv.z, kv.w};
            #pragma unroll
            for (int ii = 0; ii < 4; ii++)
                #pragma unroll
                for (int jj = 0; jj < 4; jj++) s[ii][jj] += qa[ii] * ka[jj];
        }
        bool diag = (mb == qb);
        #pragma unroll
        for (int ii = 0; ii < 4; ii++) {
            int gi = q0 + ty*4 + ii;
            float o_[4];
            #pragma unroll
            for (int jj = 0; jj < 4; jj++) {
                int gm = m0 + tx*4 + jj;
                float r = silu_f(s[ii][jj]) * (1.0f / NN);
                if (diag && gm > gi) r = 0.0f;
                o_[jj] = r;
            }
            *(float4*)(&Ss[(ty*4 + ii)*ALD + tx*4]) =
                make_float4(o_[0], o_[1], o_[2], o_[3]);
        }
        __syncthreads();

        // O += S V
        #pragma unroll 8
        for (int m = 0; m < 64; m++) {
            float4 vv = *(const float4*)(&Vs[m*ALD + tx*4]);
            float s0 = Ss[(ty*4+0)*ALD + m];
            float s1 = Ss[(ty*4+1)*ALD + m];
            float s2 = Ss[(ty*4+2)*ALD + m];
            float s3 = Ss[(ty*4+3)*ALD + m];
            acc[0][0] += s0*vv.x; acc[0][1] += s0*vv.y; acc[0][2] += s0*vv.z; acc[0][3] += s0*vv.w;
            acc[1][0] += s1*vv.x; acc[1][1] += s1*vv.y; acc[1][2] += s1*vv.z; acc[1][3] += s1*vv.w;
            acc[2][0] += s2*vv.x; acc[2][1] += s2*vv.y; acc[2][2] += s2*vv.z; acc[2][3] += s2*vv.w;
            acc[3][0] += s3*vv.x; acc[3][1] += s3*vv.y; acc[3][2] += s3*vv.z; acc[3][3] += s3*vv.w;
        }
        __syncthreads();
    }

    #pragma unroll
    for (int ii = 0; ii < 4; ii++) {
        size_t gr = (size_t)b * NN + q0 + ty*4 + ii;
        *(float4*)(g_attn + gr * DD + h*64 + tx*4) =
            make_float4(acc[ii][0], acc[ii][1], acc[ii][2], acc[ii][3]);
    }
}

// ---------------- LN(attn) * u -> g_oin -------------------------------------
__global__ void ln_attn_kernel() {
    int row = blockIdx.x;
    int t = threadIdx.x;
    float4 v = ((const float4*)(g_attn + (size_t)row * DD))[t];
    float s  = v.x + v.y + v.z + v.w;
    float ss = v.x*v.x + v.y*v.y + v.z*v.z + v.w*v.w;
    #pragma unroll
    for (int o = 16; o; o >>= 1) {
        s  += __shfl_xor_sync(0xffffffffu, s,  o);
        ss += __shfl_xor_sync(0xffffffffu, ss, o);
    }
    __shared__ float shs[4], shq[4];
    if ((t & 31) == 0) { shs[t >> 5] = s; shq[t >> 5] = ss; }
    __syncthreads();
    s  = shs[0] + shs[1] + shs[2] + shs[3];
    ss = shq[0] + shq[1] + shq[2] + shq[3];
    float mu  = s * (1.0f / DD);
    float var = ss * (1.0f / DD) - mu * mu;
    float rs  = rsqrtf(var + 1e-6f);
    float4 u = ((const float4*)(g_proj + (size_t)row * EE))[t];  // u = cols [0,512)
    float4 o;
    o.x = (v.x - mu) * rs * u.x; o.y = (v.y - mu) * rs * u.y;
    o.z = (v.z - mu) * rs * u.z; o.w = (v.w - mu) * rs * u.w;
    ((float4*)(g_oin + (size_t)row * DD))[t] = o;
}

// ---------------- GEMM2: out = g_oin @ o_w^T + o_b + x ----------------------
__global__ __launch_bounds__(256) void gemm_out_kernel(
    const float* __restrict__ Wo, const float* __restrict__ bias,
    const float* __restrict__ x, float* __restrict__ out) {
    __shared__ float As[16][128];
    __shared__ float Bs[16][128];
    int bn = blockIdx.x * 128, bm = blockIdx.y * 128;
    int tid = threadIdx.x, tx = tid & 15, ty = tid >> 4;
    float acc[8][8] = {};
    for (int k0 = 0; k0 < DD; k0 += 16) {
        #pragma unroll
        for (int i = 0; i < 2; i++) {
            int idx = tid * 2 + i;
            int r = idx >> 2, c = idx & 3;
            float4 a = *(const float4*)(g_oin + (size_t)(bm + r) * DD + k0 + c * 4);
            As[c*4+0][r] = a.x; As[c*4+1][r] = a.y;
            As[c*4+2][r] = a.z; As[c*4+3][r] = a.w;
            // o_w is [D, F] row-major; contraction over F -> load transposed
            float4 w = *(const float4*)(Wo + (size_t)(bn + r) * DD + k0 + c * 4);
            Bs[c*4+0][r] = w.x; Bs[c*4+1][r] = w.y;
            Bs[c*4+2][r] = w.z; Bs[c*4+3][r] = w.w;
        }
        __syncthreads();
        #pragma unroll
        for (int k = 0; k < 16; k++) {
            float a[8], b[8];
            *(float4*)(a)     = *(const float4*)(&As[k][ty*8]);
            *(float4*)(a + 4) = *(const float4*)(&As[k][ty*8 + 4]);
            *(float4*)(b)     = *(const float4*)(&Bs[k][tx*8]);
            *(float4*)(b + 4) = *(const float4*)(&Bs[k][tx*8 + 4]);
            #pragma unroll
            for (int i = 0; i < 8; i++)
                #pragma unroll
                for (int j = 0; j < 8; j++) acc[i][j] += a[i] * b[j];
        }
        __syncthreads();
    }
    #pragma unroll
    for (int i = 0; i < 8; i++) {
        size_t row = (size_t)(bm + ty*8 + i);
        int col = bn + tx*8;
        float4 x0 = *(const float4*)(x + row * DD + col);
        float4 x1 = *(const float4*)(x + row * DD + col + 4);
        float4 b0 = *(const float4*)(bias + col);
        float4 b1 = *(const float4*)(bias + col + 4);
        float4 o0, o1;
        o0.x = acc[i][0] + b0.x + x0.x; o0.y = acc[i][1] + b0.y + x0.y;
        o0.z = acc[i][2] + b0.z + x0.z; o0.w = acc[i][3] + b0.w + x0.w;
        o1.x = acc[i][4] + b1.x + x1.x; o1.y = acc[i][5] + b1.y + x1.y;
        o1.z = acc[i][6] + b1.z + x1.z; o1.w = acc[i][7] + b1.w + x1.w;
        float* op = out + row * DD + col;
        *(float4*)op = o0; *(float4*)(op + 4) = o1;
    }
}

// ---------------- launch -----------------------------------------------------
extern "C" void kernel_launch(void* const* d_in, const int* in_sizes, int n_in,
                              void* d_out, int out_size) {
    const float* x    = (const float*)d_in[0];
    // d_in[1] = invalid_attn_mask (tril causal) -- implemented analytically
    const float* uvqk = (const float*)d_in[2];
    const float* o_w  = (const float*)d_in[3];
    const float* o_b  = (const float*)d_in[4];
    float* out = (float*)d_out;

    ln_x_kernel<<<RR, 128>>>(x);

    dim3 g1(EE / 128, RR / 128);
    gemm_proj_kernel<<<g1, 256>>>(uvqk);

    cudaFuncSetAttribute(attn_kernel,
                         cudaFuncAttributeMaxDynamicSharedMemorySize,
                         ATT_SMEM_BYTES);
    dim3 ga(NN / 64, HH, BB);
    attn_kernel<<<ga, 256, ATT_SMEM_BYTES>>>();

    ln_attn_kernel<<<RR, 128>>>();

    dim3 g2(DD / 128, RR / 128);
    gemm_out_kernel<<<g2, 256>>>(o_w, o_b, x, out);
}

// round 5
// speedup vs baseline: 1.8945x; 1.8945x over previous
#include <cuda_runtime.h>
#include <math.h>
#include <stdint.h>

#define BB 4
#define NN 2048
#define DD 512
#define HH 8
#define RR (BB*NN)   // 8192 rows
#define EE 2048      // proj width

// ---------------- scratch (static device globals; no allocation) -------------
__device__ float g_norm[(size_t)RR*DD];   // 16 MB  LN(x)
__device__ float g_proj[(size_t)RR*EE];   // 64 MB  silu(normX @ uvqk) = [u|v|q|k]
__device__ float g_attn[(size_t)RR*DD];   // 16 MB  attention output (H*dL=512)
__device__ float g_oin [(size_t)RR*DD];   // 16 MB  u * LN(attn)

__device__ __forceinline__ float silu_f(float v) { return v / (1.0f + expf(-v)); }

__device__ __forceinline__ float tf32r(float x) {
    uint32_t u;
    asm("cvt.rna.tf32.f32 %0, %1;" : "=r"(u) : "f"(x));
    return __uint_as_float(u);
}

// mma.sync m16n8k8 row.col tf32, fp32 accumulate (in place)
__device__ __forceinline__ void mma8(float* d, const float* a, const float* b) {
    asm volatile(
        "mma.sync.aligned.m16n8k8.row.col.f32.tf32.tf32.f32 "
        "{%0,%1,%2,%3}, {%4,%5,%6,%7}, {%8,%9}, {%0,%1,%2,%3};"
        : "+f"(d[0]), "+f"(d[1]), "+f"(d[2]), "+f"(d[3])
        : "r"(__float_as_uint(a[0])), "r"(__float_as_uint(a[1])),
          "r"(__float_as_uint(a[2])), "r"(__float_as_uint(a[3])),
          "r"(__float_as_uint(b[0])), "r"(__float_as_uint(b[1])));
}

// ---------------- LayerNorm of x -> g_norm  (1 block / row, 128 thr) ---------
__global__ void ln_x_kernel(const float* __restrict__ x) {
    int row = blockIdx.x;
    int t = threadIdx.x;
    float4 v = ((const float4*)(x + (size_t)row * DD))[t];
    float s  = v.x + v.y + v.z + v.w;
    float ss = v.x*v.x + v.y*v.y + v.z*v.z + v.w*v.w;
    #pragma unroll
    for (int o = 16; o; o >>= 1) {
        s  += __shfl_xor_sync(0xffffffffu, s,  o);
        ss += __shfl_xor_sync(0xffffffffu, ss, o);
    }
    __shared__ float shs[4], shq[4];
    if ((t & 31) == 0) { shs[t >> 5] = s; shq[t >> 5] = ss; }
    __syncthreads();
    s  = shs[0] + shs[1] + shs[2] + shs[3];
    ss = shq[0] + shq[1] + shq[2] + shq[3];
    float mu  = s * (1.0f / DD);
    float var = ss * (1.0f / DD) - mu * mu;
    float rs  = rsqrtf(var + 1e-6f);
    float4 o;
    o.x = (v.x - mu) * rs; o.y = (v.y - mu) * rs;
    o.z = (v.z - mu) * rs; o.w = (v.w - mu) * rs;
    ((float4*)(g_norm + (size_t)row * DD))[t] = o;
}

// ============================================================================
// GEMM1: g_proj = silu(g_norm[8192x512] @ uvqk[512x2048])   (tf32 mma.sync)
// CTA 128x128xk32, 256 thr = 8 warps (2m x 4n), warp tile 64x32
// ============================================================================
#define GLD 36

__global__ __launch_bounds__(256) void gemm_proj_kernel(const float* __restrict__ W) {
    __shared__ float As[128 * GLD];
    __shared__ float Bt[128 * GLD];   // transposed: Bt[n][k]
    int bn = blockIdx.x * 128, bm = blockIdx.y * 128;
    int tid = threadIdx.x, lane = tid & 31, warpId = tid >> 5;
    int g = lane >> 2, tig = lane & 3;
    int wm = warpId >> 2, wn = warpId & 3;
    float acc[4][4][4] = {};

    for (int k0 = 0; k0 < DD; k0 += 32) {
        __syncthreads();
        #pragma unroll
        for (int t = 0; t < 4; t++) {
            int idx = tid + t * 256;
            // A: 128 rows x 32 cols
            int r = idx >> 3, cc = idx & 7;
            float4 a = *(const float4*)(g_norm + (size_t)(bm + r) * DD + k0 + cc * 4);
            *(float4*)(As + r * GLD + cc * 4) =
                make_float4(tf32r(a.x), tf32r(a.y), tf32r(a.z), tf32r(a.w));
            // B: W[k][n] row-major -> transpose into Bt[n][k]
            int kr = idx >> 5, nc = idx & 31;
            float4 wv = *(const float4*)(W + (size_t)(k0 + kr) * EE + bn + nc * 4);
            Bt[(nc*4+0) * GLD + kr] = tf32r(wv.x);
            Bt[(nc*4+1) * GLD + kr] = tf32r(wv.y);
            Bt[(nc*4+2) * GLD + kr] = tf32r(wv.z);
            Bt[(nc*4+3) * GLD + kr] = tf32r(wv.w);
        }
        __syncthreads();
        #pragma unroll
        for (int ks = 0; ks < 4; ks++) {
            int col = ks * 8 + tig;
            float afr[4][4];
            #pragma unroll
            for (int mt = 0; mt < 4; mt++) {
                int r = wm * 64 + mt * 16 + g;
                afr[mt][0] = As[r * GLD + col];
                afr[mt][1] = As[(r + 8) * GLD + col];
                afr[mt][2] = As[r * GLD + col + 4];
                afr[mt][3] = As[(r + 8) * GLD + col + 4];
            }
            #pragma unroll
            for (int nt = 0; nt < 4; nt++) {
                int rn = wn * 32 + nt * 8 + g;
                float bfr[2] = { Bt[rn * GLD + col], Bt[rn * GLD + col + 4] };
                #pragma unroll
                for (int mt = 0; mt < 4; mt++) mma8(acc[mt][nt], afr[mt], bfr);
            }
        }
    }
    #pragma unroll
    for (int mt = 0; mt < 4; mt++) {
        int m0 = bm + wm * 64 + mt * 16 + g;
        #pragma unroll
        for (int nt = 0; nt < 4; nt++) {
            int n = bn + wn * 32 + nt * 8 + 2 * tig;
            *(float2*)(g_proj + (size_t)m0 * EE + n) =
                make_float2(silu_f(acc[mt][nt][0]), silu_f(acc[mt][nt][1]));
            *(float2*)(g_proj + (size_t)(m0 + 8) * EE + n) =
                make_float2(silu_f(acc[mt][nt][2]), silu_f(acc[mt][nt][3]));
        }
    }
}

// ============================================================================
// HSTU attention with tf32 mma.sync
// per (b,h,64-qblock), 128 thr = 4 warps, warp owns 16 q-rows.
// Phase1 S=QK^T -> silu/N + causal -> Ss (per-warp rows) -> Phase2 O+=S V
// ============================================================================
#define ALD 68
#define ATT_SMEM_BYTES (4 * 64 * ALD * (int)sizeof(float))

__global__ __launch_bounds__(128) void attn_kernel() {
    extern __shared__ float sm[];
    float* Qs = sm;                 // [64][ALD] rows=q, cols=d
    float* Ks = Qs + 64 * ALD;      // [64][ALD] rows=m, cols=d
    float* Vt = Ks + 64 * ALD;      // [64][ALD] rows=d, cols=m
    float* Ss = Vt + 64 * ALD;      // [64][ALD] rows=q, cols=m
    int qb = (int)(gridDim.x - 1 - blockIdx.x);
    int h = blockIdx.y, b = blockIdx.z;
    int tid = threadIdx.x;
    int w = tid >> 5, lane = tid & 31, g = lane >> 2, tig = lane & 3;
    const float* base = g_proj + (size_t)b * NN * EE;
    const float* Qg = base + 1024 + h * 64;
    const float* Kg = base + 1536 + h * 64;
    const float* Vg = base + 512  + h * 64;
    int q0 = qb * 64;
    int arow = w * 16 + g;

    // load Q block (rounded to tf32)
    #pragma unroll
    for (int t = 0; t < 8; t++) {
        int idx = tid + t * 128;            // 1024 float4
        int r = idx >> 4, c = idx & 15;
        float4 q = *(const float4*)(Qg + (size_t)(q0 + r) * EE + c * 4);
        *(float4*)(Qs + r * ALD + c * 4) =
            make_float4(tf32r(q.x), tf32r(q.y), tf32r(q.z), tf32r(q.w));
    }

    float oacc[8][4] = {};

    for (int mb = 0; mb <= qb; mb++) {
        int m0 = mb * 64;
        __syncthreads();
        #pragma unroll
        for (int t = 0; t < 8; t++) {
            int idx = tid + t * 128;
            int r = idx >> 4, c = idx & 15;
            float4 kq = *(const float4*)(Kg + (size_t)(m0 + r) * EE + c * 4);
            *(float4*)(Ks + r * ALD + c * 4) =
                make_float4(tf32r(kq.x), tf32r(kq.y), tf32r(kq.z), tf32r(kq.w));
            float4 vq = *(const float4*)(Vg + (size_t)(m0 + r) * EE + c * 4);
            Vt[(c*4+0) * ALD + r] = tf32r(vq.x);
            Vt[(c*4+1) * ALD + r] = tf32r(vq.y);
            Vt[(c*4+2) * ALD + r] = tf32r(vq.z);
            Vt[(c*4+3) * ALD + r] = tf32r(vq.w);
        }
        __syncthreads();

        // Phase 1: S = Q K^T
        float sacc[8][4] = {};
        #pragma unroll
        for (int kt = 0; kt < 8; kt++) {
            int col = kt * 8 + tig;
            float a[4] = { Qs[arow * ALD + col], Qs[(arow + 8) * ALD + col],
                           Qs[arow * ALD + col + 4], Qs[(arow + 8) * ALD + col + 4] };
            #pragma unroll
            for (int nt = 0; nt < 8; nt++) {
                float bfr[2] = { Ks[(nt*8 + g) * ALD + col],
                                 Ks[(nt*8 + g) * ALD + col + 4] };
                mma8(sacc[nt], a, bfr);
            }
        }

        // silu + scale + causal mask, round to tf32, write P to Ss (own rows)
        bool diag = (mb == qb);
        int r0g = q0 + arow, r1g = r0g + 8;
        #pragma unroll
        for (int nt = 0; nt < 8; nt++) {
            int c0g = m0 + nt * 8 + 2 * tig, c1g = c0g + 1;
            float p0 = silu_f(sacc[nt][0]) * (1.0f / NN);
            float p1 = silu_f(sacc[nt][1]) * (1.0f / NN);
            float p2 = silu_f(sacc[nt][2]) * (1.0f / NN);
            float p3 = silu_f(sacc[nt][3]) * (1.0f / NN);
            if (diag) {
                if (c0g > r0g) p0 = 0.0f;
                if (c1g > r0g) p1 = 0.0f;
                if (c0g > r1g) p2 = 0.0f;
                if (c1g > r1g) p3 = 0.0f;
            }
            *(float2*)(Ss + arow * ALD + nt * 8 + 2 * tig) =
                make_float2(tf32r(p0), tf32r(p1));
            *(float2*)(Ss + (arow + 8) * ALD + nt * 8 + 2 * tig) =
                make_float2(tf32r(p2), tf32r(p3));
        }
        __syncwarp();

        // Phase 2: O += P V   (k = m index)
        #pragma unroll
        for (int kt = 0; kt < 8; kt++) {
            int col = kt * 8 + tig;
            float a[4] = { Ss[arow * ALD + col], Ss[(arow + 8) * ALD + col],
                           Ss[arow * ALD + col + 4], Ss[(arow + 8) * ALD + col + 4] };
            #pragma unroll
            for (int nt = 0; nt < 8; nt++) {
                float bfr[2] = { Vt[(nt*8 + g) * ALD + col],
                                 Vt[(nt*8 + g) * ALD + col + 4] };
                mma8(oacc[nt], a, bfr);
            }
        }
        __syncwarp();
    }

    // store O
    size_t row0 = (size_t)b * NN + q0 + arow;
    #pragma unroll
    for (int nt = 0; nt < 8; nt++) {
        int n = h * 64 + nt * 8 + 2 * tig;
        *(float2*)(g_attn + row0 * DD + n) = make_float2(oacc[nt][0], oacc[nt][1]);
        *(float2*)(g_attn + (row0 + 8) * DD + n) = make_float2(oacc[nt][2], oacc[nt][3]);
    }
}

// ---------------- LN(attn) * u -> g_oin -------------------------------------
__global__ void ln_attn_kernel() {
    int row = blockIdx.x;
    int t = threadIdx.x;
    float4 v = ((const float4*)(g_attn + (size_t)row * DD))[t];
    float s  = v.x + v.y + v.z + v.w;
    float ss = v.x*v.x + v.y*v.y + v.z*v.z + v.w*v.w;
    #pragma unroll
    for (int o = 16; o; o >>= 1) {
        s  += __shfl_xor_sync(0xffffffffu, s,  o);
        ss += __shfl_xor_sync(0xffffffffu, ss, o);
    }
    __shared__ float shs[4], shq[4];
    if ((t & 31) == 0) { shs[t >> 5] = s; shq[t >> 5] = ss; }
    __syncthreads();
    s  = shs[0] + shs[1] + shs[2] + shs[3];
    ss = shq[0] + shq[1] + shq[2] + shq[3];
    float mu  = s * (1.0f / DD);
    float var = ss * (1.0f / DD) - mu * mu;
    float rs  = rsqrtf(var + 1e-6f);
    float4 u = ((const float4*)(g_proj + (size_t)row * EE))[t];
    float4 o;
    o.x = (v.x - mu) * rs * u.x; o.y = (v.y - mu) * rs * u.y;
    o.z = (v.z - mu) * rs * u.z; o.w = (v.w - mu) * rs * u.w;
    ((float4*)(g_oin + (size_t)row * DD))[t] = o;
}

// ============================================================================
// GEMM2: out = g_oin[8192x512] @ o_w^T[512x512] + o_b + x   (tf32 mma.sync)
// o_w is [Dout, F] row-major, contraction over F -> o_w rows ARE B cols (k-contig)
// ============================================================================
__global__ __launch_bounds__(256) void gemm_out_kernel(
    const float* __restrict__ Wo, const float* __restrict__ bias,
    const float* __restrict__ x, float* __restrict__ out) {
    __shared__ float As[128 * GLD];
    __shared__ float Bt[128 * GLD];
    int bn = blockIdx.x * 128, bm = blockIdx.y * 128;
    int tid = threadIdx.x, lane = tid & 31, warpId = tid >> 5;
    int g = lane >> 2, tig = lane & 3;
    int wm = warpId >> 2, wn = warpId & 3;
    float acc[4][4][4] = {};

    for (int k0 = 0; k0 < DD; k0 += 32) {
        __syncthreads();
        #pragma unroll
        for (int t = 0; t < 4; t++) {
            int idx = tid + t * 256;
            int r = idx >> 3, cc = idx & 7;
            float4 a = *(const float4*)(g_oin + (size_t)(bm + r) * DD + k0 + cc * 4);
            *(float4*)(As + r * GLD + cc * 4) =
                make_float4(tf32r(a.x), tf32r(a.y), tf32r(a.z), tf32r(a.w));
            float4 wv = *(const float4*)(Wo + (size_t)(bn + r) * DD + k0 + cc * 4);
            *(float4*)(Bt + r * GLD + cc * 4) =
                make_float4(tf32r(wv.x), tf32r(wv.y), tf32r(wv.z), tf32r(wv.w));
        }
        __syncthreads();
        #pragma unroll
        for (int ks = 0; ks < 4; ks++) {
            int col = ks * 8 + tig;
            float afr[4][4];
            #pragma unroll
            for (int mt = 0; mt < 4; mt++) {
                int r = wm * 64 + mt * 16 + g;
                afr[mt][0] = As[r * GLD + col];
                afr[mt][1] = As[(r + 8) * GLD + col];
                afr[mt][2] = As[r * GLD + col + 4];
                afr[mt][3] = As[(r + 8) * GLD + col + 4];
            }
            #pragma unroll
            for (int nt = 0; nt < 4; nt++) {
                int rn = wn * 32 + nt * 8 + g;
                float bfr[2] = { Bt[rn * GLD + col], Bt[rn * GLD + col + 4] };
                #pragma unroll
                for (int mt = 0; mt < 4; mt++) mma8(acc[mt][nt], afr[mt], bfr);
            }
        }
    }
    #pragma unroll
    for (int mt = 0; mt < 4; mt++) {
        size_t m0 = (size_t)(bm + wm * 64 + mt * 16 + g);
        #pragma unroll
        for (int nt = 0; nt < 4; nt++) {
            int n = bn + wn * 32 + nt * 8 + 2 * tig;
            float2 b2 = *(const float2*)(bias + n);
            float2 x0 = *(const float2*)(x + m0 * DD + n);
            float2 x1 = *(const float2*)(x + (m0 + 8) * DD + n);
            *(float2*)(out + m0 * DD + n) =
                make_float2(acc[mt][nt][0] + b2.x + x0.x,
                            acc[mt][nt][1] + b2.y + x0.y);
            *(float2*)(out + (m0 + 8) * DD + n) =
                make_float2(acc[mt][nt][2] + b2.x + x1.x,
                            acc[mt][nt][3] + b2.y + x1.y);
        }
    }
}

// ---------------- launch -----------------------------------------------------
extern "C" void kernel_launch(void* const* d_in, const int* in_sizes, int n_in,
                              void* d_out, int out_size) {
    const float* x    = (const float*)d_in[0];
    // d_in[1] = invalid_attn_mask (tril causal) -- implemented analytically
    const float* uvqk = (const float*)d_in[2];
    const float* o_w  = (const float*)d_in[3];
    const float* o_b  = (const float*)d_in[4];
    float* out = (float*)d_out;

    ln_x_kernel<<<RR, 128>>>(x);

    dim3 g1(EE / 128, RR / 128);
    gemm_proj_kernel<<<g1, 256>>>(uvqk);

    cudaFuncSetAttribute(attn_kernel,
                         cudaFuncAttributeMaxDynamicSharedMemorySize,
                         ATT_SMEM_BYTES);
    dim3 ga(NN / 64, HH, BB);
    attn_kernel<<<ga, 128, ATT_SMEM_BYTES>>>();

    ln_attn_kernel<<<RR, 128>>>();

    dim3 g2(DD / 128, RR / 128);
    gemm_out_kernel<<<g2, 256>>>(o_w, o_b, x, out);
}

// round 7
// speedup vs baseline: 2.2132x; 1.1683x over previous
#include <cuda_runtime.h>
#include <math.h>
#include <stdint.h>

#define BB 4
#define NN 2048
#define DD 512
#define HH 8
#define RR (BB*NN)   // 8192 rows
#define EE 2048      // proj width

// ---------------- scratch (static device globals; no allocation) -------------
__device__ float g_norm[(size_t)RR*DD];   // 16 MB  LN(x)
__device__ float g_proj[(size_t)RR*EE];   // 64 MB  silu(normX @ uvqk) = [u|v|q|k]
__device__ float g_attn[(size_t)RR*DD];   // 16 MB  attention output
__device__ float g_oin [(size_t)RR*DD];   // 16 MB  u * LN(attn)

__device__ __forceinline__ float silu_f(float v) { return v / (1.0f + expf(-v)); }

__device__ __forceinline__ float tf32r(float x) {
    uint32_t u;
    asm("cvt.rna.tf32.f32 %0, %1;" : "=r"(u) : "f"(x));
    return __uint_as_float(u);
}

// mma.sync m16n8k8 row.col tf32, fp32 accumulate (in place)
__device__ __forceinline__ void mma8(float* d, const float* a, const float* b) {
    asm volatile(
        "mma.sync.aligned.m16n8k8.row.col.f32.tf32.tf32.f32 "
        "{%0,%1,%2,%3}, {%4,%5,%6,%7}, {%8,%9}, {%0,%1,%2,%3};"
        : "+f"(d[0]), "+f"(d[1]), "+f"(d[2]), "+f"(d[3])
        : "r"(__float_as_uint(a[0])), "r"(__float_as_uint(a[1])),
          "r"(__float_as_uint(a[2])), "r"(__float_as_uint(a[3])),
          "r"(__float_as_uint(b[0])), "r"(__float_as_uint(b[1])));
}

__device__ __forceinline__ void cpa16(float* dst_smem, const float* src) {
    uint32_t d = (uint32_t)__cvta_generic_to_shared(dst_smem);
    asm volatile("cp.async.cg.shared.global [%0], [%1], 16;\n" :: "r"(d), "l"(src));
}
#define CP_COMMIT() asm volatile("cp.async.commit_group;\n" ::: "memory")
#define CP_WAIT1()  asm volatile("cp.async.wait_group 1;\n" ::: "memory")
#define CP_WAIT0()  asm volatile("cp.async.wait_group 0;\n" ::: "memory")

// ---------------- LayerNorm of x -> g_norm  (1 block / row, 128 thr) ---------
__global__ void ln_x_kernel(const float* __restrict__ x) {
    int row = blockIdx.x;
    int t = threadIdx.x;
    float4 v = ((const float4*)(x + (size_t)row * DD))[t];
    float s  = v.x + v.y + v.z + v.w;
    float ss = v.x*v.x + v.y*v.y + v.z*v.z + v.w*v.w;
    #pragma unroll
    for (int o = 16; o; o >>= 1) {
        s  += __shfl_xor_sync(0xffffffffu, s,  o);
        ss += __shfl_xor_sync(0xffffffffu, ss, o);
    }
    __shared__ float shs[4], shq[4];
    if ((t & 31) == 0) { shs[t >> 5] = s; shq[t >> 5] = ss; }
    __syncthreads();
    s  = shs[0] + shs[1] + shs[2] + shs[3];
    ss = shq[0] + shq[1] + shq[2] + shq[3];
    float mu  = s * (1.0f / DD);
    float var = ss * (1.0f / DD) - mu * mu;
    float rs  = rsqrtf(var + 1e-6f);
    float4 o;
    o.x = (v.x - mu) * rs; o.y = (v.y - mu) * rs;
    o.z = (v.z - mu) * rs; o.w = (v.w - mu) * rs;
    ((float4*)(g_norm + (size_t)row * DD))[t] = o;
}

// ============================================================================
// GEMM1: g_proj = silu(g_norm[8192x512] @ uvqk[512x2048])
// tf32 mma.sync, cp.async 2-stage pipeline, CTA 128x128xk32, 8 warps (2m x 4n)
// smem: As[128][36] (m-major), Bs[32][136] (k-major, W rows as-is)
// ============================================================================
#define AL 36
#define BL 136
#define G1_ASZ (128*AL)
#define G1_BSZ (32*BL)
#define G1_SMEM ((G1_ASZ + G1_BSZ) * 2 * (int)sizeof(float))

__global__ __launch_bounds__(256) void gemm_proj_kernel(const float* __restrict__ W) {
    extern __shared__ float smg[];
    float* As[2] = { smg, smg + G1_ASZ };
    float* Bs[2] = { smg + 2*G1_ASZ, smg + 2*G1_ASZ + G1_BSZ };
    int bn = blockIdx.x * 128, bm = blockIdx.y * 128;
    int tid = threadIdx.x, lane = tid & 31, warpId = tid >> 5;
    int g = lane >> 2, tig = lane & 3;
    int wm = warpId >> 2, wn = warpId & 3;
    float acc[4][4][4] = {};

    // stage loader: A 1024 chunks + B 1024 chunks, 8 per thread
    auto load_stage = [&](int s, int k0) {
        #pragma unroll
        for (int t = 0; t < 4; t++) {
            int idx = tid + t * 256;
            int r = idx >> 3, c4 = idx & 7;
            cpa16(As[s] + r * AL + c4 * 4,
                  g_norm + (size_t)(bm + r) * DD + k0 + c4 * 4);
        }
        #pragma unroll
        for (int t = 0; t < 4; t++) {
            int idx = tid + t * 256;
            int kr = idx >> 5, nc = idx & 31;
            cpa16(Bs[s] + kr * BL + nc * 4,
                  W + (size_t)(k0 + kr) * EE + bn + nc * 4);
        }
        CP_COMMIT();
    };

    load_stage(0, 0);
    const int NK = DD / 32;
    for (int it = 0; it < NK; it++) {
        if (it + 1 < NK) { load_stage((it + 1) & 1, (it + 1) * 32); CP_WAIT1(); }
        else CP_WAIT0();
        __syncthreads();
        const float* Ap = As[it & 1];
        const float* Bp = Bs[it & 1];
        #pragma unroll
        for (int ks = 0; ks < 4; ks++) {
            int col = ks * 8 + tig;
            float afr[4][4];
            #pragma unroll
            for (int mt = 0; mt < 4; mt++) {
                int r = wm * 64 + mt * 16 + g;
                afr[mt][0] = tf32r(Ap[r * AL + col]);
                afr[mt][1] = tf32r(Ap[(r + 8) * AL + col]);
                afr[mt][2] = tf32r(Ap[r * AL + col + 4]);
                afr[mt][3] = tf32r(Ap[(r + 8) * AL + col + 4]);
            }
            #pragma unroll
            for (int nt = 0; nt < 4; nt++) {
                int rn = wn * 32 + nt * 8 + g;
                float bfr[2] = { tf32r(Bp[col * BL + rn]),
                                 tf32r(Bp[(col + 4) * BL + rn]) };
                #pragma unroll
                for (int mt = 0; mt < 4; mt++) mma8(acc[mt][nt], afr[mt], bfr);
            }
        }
        __syncthreads();
    }
    #pragma unroll
    for (int mt = 0; mt < 4; mt++) {
        int m0 = bm + wm * 64 + mt * 16 + g;
        #pragma unroll
        for (int nt = 0; nt < 4; nt++) {
            int n = bn + wn * 32 + nt * 8 + 2 * tig;
            *(float2*)(g_proj + (size_t)m0 * EE + n) =
                make_float2(silu_f(acc[mt][nt][0]), silu_f(acc[mt][nt][1]));
            *(float2*)(g_proj + (size_t)(m0 + 8) * EE + n) =
                make_float2(silu_f(acc[mt][nt][2]), silu_f(acc[mt][nt][3]));
        }
    }
}

// ============================================================================
// HSTU attention, tf32 mma.sync, 256 thr = 8 warps per 64-q-block.
// warps 0-3: cols/d 0-31, warps 4-7: cols/d 32-63; warp owns 16 q-rows.
// ============================================================================
#define ALD 68
#define ATT_SMEM_BYTES (4 * 64 * ALD * (int)sizeof(float))

__global__ __launch_bounds__(256) void attn_kernel() {
    extern __shared__ float sm[];
    float* Qs = sm;                 // [64][ALD] rows=q, cols=d
    float* Ks = Qs + 64 * ALD;      // [64][ALD] rows=m, cols=d
    float* Vt = Ks + 64 * ALD;      // [64][ALD] rows=d, cols=m
    float* Ss = Vt + 64 * ALD;      // [64][ALD] rows=q, cols=m
    int qb = (int)(gridDim.x - 1 - blockIdx.x);
    int h = blockIdx.y, b = blockIdx.z;
    int tid = threadIdx.x;
    int w = tid >> 5, lane = tid & 31, g = lane >> 2, tig = lane & 3;
    int half = w >> 2, wr = w & 3;
    const float* base = g_proj + (size_t)b * NN * EE;
    const float* Qg = base + 1024 + h * 64;
    const float* Kg = base + 1536 + h * 64;
    const float* Vg = base + 512  + h * 64;
    int q0 = qb * 64;
    int arow = wr * 16 + g;

    // load Q block (rounded to tf32): 1024 float4 chunks over 256 threads
    #pragma unroll
    for (int t = 0; t < 4; t++) {
        int idx = tid + t * 256;
        int r = idx >> 4, c = idx & 15;
        float4 q = *(const float4*)(Qg + (size_t)(q0 + r) * EE + c * 4);
        *(float4*)(Qs + r * ALD + c * 4) =
            make_float4(tf32r(q.x), tf32r(q.y), tf32r(q.z), tf32r(q.w));
    }

    float oacc[4][4] = {};

    for (int mb = 0; mb <= qb; mb++) {
        int m0 = mb * 64;
        __syncthreads();
        #pragma unroll
        for (int t = 0; t < 4; t++) {
            int idx = tid + t * 256;
            int r = idx >> 4, c = idx & 15;
            float4 kq = *(const float4*)(Kg + (size_t)(m0 + r) * EE + c * 4);
            *(float4*)(Ks + r * ALD + c * 4) =
                make_float4(tf32r(kq.x), tf32r(kq.y), tf32r(kq.z), tf32r(kq.w));
            float4 vq = *(const float4*)(Vg + (size_t)(m0 + r) * EE + c * 4);
            Vt[(c*4+0) * ALD + r] = tf32r(vq.x);
            Vt[(c*4+1) * ALD + r] = tf32r(vq.y);
            Vt[(c*4+2) * ALD + r] = tf32r(vq.z);
            Vt[(c*4+3) * ALD + r] = tf32r(vq.w);
        }
        __syncthreads();

        // Phase 1: S = Q K^T  (this warp covers n-cols [half*32, half*32+32))
        float sacc[4][4] = {};
        #pragma unroll
        for (int kt = 0; kt < 8; kt++) {
            int col = kt * 8 + tig;
            float a[4] = { Qs[arow * ALD + col], Qs[(arow + 8) * ALD + col],
                           Qs[arow * ALD + col + 4], Qs[(arow + 8) * ALD + col + 4] };
            #pragma unroll
            for (int nt = 0; nt < 4; nt++) {
                int rn = half * 32 + nt * 8 + g;
                float bfr[2] = { Ks[rn * ALD + col], Ks[rn * ALD + col + 4] };
                mma8(sacc[nt], a, bfr);
            }
        }

        // silu + scale + causal mask, round to tf32, write P tile region
        bool diag = (mb == qb);
        int r0g = q0 + arow, r1g = r0g + 8;
        #pragma unroll
        for (int nt = 0; nt < 4; nt++) {
            int cb = half * 32 + nt * 8 + 2 * tig;
            int c0g = m0 + cb, c1g = c0g + 1;
            float p0 = silu_f(sacc[nt][0]) * (1.0f / NN);
            float p1 = silu_f(sacc[nt][1]) * (1.0f / NN);
            float p2 = silu_f(sacc[nt][2]) * (1.0f / NN);
            float p3 = silu_f(sacc[nt][3]) * (1.0f / NN);
            if (diag) {
                if (c0g > r0g) p0 = 0.0f;
                if (c1g > r0g) p1 = 0.0f;
                if (c0g > r1g) p2 = 0.0f;
                if (c1g > r1g) p3 = 0.0f;
            }
            *(float2*)(Ss + arow * ALD + cb) = make_float2(tf32r(p0), tf32r(p1));
            *(float2*)(Ss + (arow + 8) * ALD + cb) = make_float2(tf32r(p2), tf32r(p3));
        }
        __syncthreads();   // P columns come from both warp halves

        // Phase 2: O += P V  (this warp covers d-cols [half*32, half*32+32))
        #pragma unroll
        for (int kt = 0; kt < 8; kt++) {
            int col = kt * 8 + tig;
            float a[4] = { Ss[arow * ALD + col], Ss[(arow + 8) * ALD + col],
                           Ss[arow * ALD + col + 4], Ss[(arow + 8) * ALD + col + 4] };
            #pragma unroll
            for (int nt = 0; nt < 4; nt++) {
                int rn = half * 32 + nt * 8 + g;
                float bfr[2] = { Vt[rn * ALD + col], Vt[rn * ALD + col + 4] };
                mma8(oacc[nt], a, bfr);
            }
        }
    }

    // store O
    size_t row0 = (size_t)b * NN + q0 + arow;
    #pragma unroll
    for (int nt = 0; nt < 4; nt++) {
        int n = h * 64 + half * 32 + nt * 8 + 2 * tig;
        *(float2*)(g_attn + row0 * DD + n) = make_float2(oacc[nt][0], oacc[nt][1]);
        *(float2*)(g_attn + (row0 + 8) * DD + n) = make_float2(oacc[nt][2], oacc[nt][3]);
    }
}

// ---------------- LN(attn) * u -> g_oin -------------------------------------
__global__ void ln_attn_kernel() {
    int row = blockIdx.x;
    int t = threadIdx.x;
    float4 v = ((const float4*)(g_attn + (size_t)row * DD))[t];
    float s  = v.x + v.y + v.z + v.w;
    float ss = v.x*v.x + v.y*v.y + v.z*v.z + v.w*v.w;
    #pragma unroll
    for (int o = 16; o; o >>= 1) {
        s  += __shfl_xor_sync(0xffffffffu, s,  o);
        ss += __shfl_xor_sync(0xffffffffu, ss, o);
    }
    __shared__ float shs[4], shq[4];
    if ((t & 31) == 0) { shs[t >> 5] = s; shq[t >> 5] = ss; }
    __syncthreads();
    s  = shs[0] + shs[1] + shs[2] + shs[3];
    ss = shq[0] + shq[1] + shq[2] + shq[3];
    float mu  = s * (1.0f / DD);
    float var = ss * (1.0f / DD) - mu * mu;
    float rs  = rsqrtf(var + 1e-6f);
    float4 u = ((const float4*)(g_proj + (size_t)row * EE))[t];
    float4 o;
    o.x = (v.x - mu) * rs * u.x; o.y = (v.y - mu) * rs * u.y;
    o.z = (v.z - mu) * rs * u.z; o.w = (v.w - mu) * rs * u.w;
    ((float4*)(g_oin + (size_t)row * DD))[t] = o;
}

// ============================================================================
// GEMM2: out = g_oin[8192x512] @ o_w^T[512x512] + o_b + x
// o_w rows are output cols, k-contiguous -> Bt[n][k] via cp.async directly
// ============================================================================
#define G2_ASZ (128*AL)
#define G2_BSZ (128*AL)
#define G2_SMEM ((G2_ASZ + G2_BSZ) * 2 * (int)sizeof(float))

__global__ __launch_bounds__(256) void gemm_out_kernel(
    const float* __restrict__ Wo, const float* __restrict__ bias,
    const float* __restrict__ x, float* __restrict__ out) {
    extern __shared__ float smg[];
    float* As[2] = { smg, smg + G2_ASZ };
    float* Bt[2] = { smg + 2*G2_ASZ, smg + 2*G2_ASZ + G2_BSZ };
    int bn = blockIdx.x * 128, bm = blockIdx.y * 128;
    int tid = threadIdx.x, lane = tid & 31, warpId = tid >> 5;
    int g = lane >> 2, tig = lane & 3;
    int wm = warpId >> 2, wn = warpId & 3;
    float acc[4][4][4] = {};

    auto load_stage = [&](int s, int k0) {
        #pragma unroll
        for (int t = 0; t < 4; t++) {
            int idx = tid + t * 256;
            int r = idx >> 3, c4 = idx & 7;
            cpa16(As[s] + r * AL + c4 * 4,
                  g_oin + (size_t)(bm + r) * DD + k0 + c4 * 4);
        }
        #pragma unroll
        for (int t = 0; t < 4; t++) {
            int idx = tid + t * 256;
            int r = idx >> 3, c4 = idx & 7;
            cpa16(Bt[s] + r * AL + c4 * 4,
                  Wo + (size_t)(bn + r) * DD + k0 + c4 * 4);
        }
        CP_COMMIT();
    };

    load_stage(0, 0);
    const int NK = DD / 32;
    for (int it = 0; it < NK; it++) {
        if (it + 1 < NK) { load_stage((it + 1) & 1, (it + 1) * 32); CP_WAIT1(); }
        else CP_WAIT0();
        __syncthreads();
        const float* Ap = As[it & 1];
        const float* Bp = Bt[it & 1];
        #pragma unroll
        for (int ks = 0; ks < 4; ks++) {
            int col = ks * 8 + tig;
            float afr[4][4];
            #pragma unroll
            for (int mt = 0; mt < 4; mt++) {
                int r = wm * 64 + mt * 16 + g;
                afr[mt][0] = tf32r(Ap[r * AL + col]);
                afr[mt][1] = tf32r(Ap[(r + 8) * AL + col]);
                afr[mt][2] = tf32r(Ap[r * AL + col + 4]);
                afr[mt][3] = tf32r(Ap[(r + 8) * AL + col + 4]);
            }
            #pragma unroll
            for (int nt = 0; nt < 4; nt++) {
                int rn = wn * 32 + nt * 8 + g;
                float bfr[2] = { tf32r(Bp[rn * AL + col]),
                                 tf32r(Bp[rn * AL + col + 4]) };
                #pragma unroll
                for (int mt = 0; mt < 4; mt++) mma8(acc[mt][nt], afr[mt], bfr);
            }
        }
        __syncthreads();
    }
    #pragma unroll
    for (int mt = 0; mt < 4; mt++) {
        size_t m0 = (size_t)(bm + wm * 64 + mt * 16 + g);
        #pragma unroll
        for (int nt = 0; nt < 4; nt++) {
            int n = bn + wn * 32 + nt * 8 + 2 * tig;
            float2 b2 = *(const float2*)(bias + n);
            float2 x0 = *(const float2*)(x + m0 * DD + n);
            float2 x1 = *(const float2*)(x + (m0 + 8) * DD + n);
            *(float2*)(out + m0 * DD + n) =
                make_float2(acc[mt][nt][0] + b2.x + x0.x,
                            acc[mt][nt][1] + b2.y + x0.y);
            *(float2*)(out + (m0 + 8) * DD + n) =
                make_float2(acc[mt][nt][2] + b2.x + x1.x,
                            acc[mt][nt][3] + b2.y + x1.y);
        }
    }
}

// ---------------- launch -----------------------------------------------------
extern "C" void kernel_launch(void* const* d_in, const int* in_sizes, int n_in,
                              void* d_out, int out_size) {
    const float* x    = (const float*)d_in[0];
    // d_in[1] = invalid_attn_mask (tril causal) -- implemented analytically
    const float* uvqk = (const float*)d_in[2];
    const float* o_w  = (const float*)d_in[3];
    const float* o_b  = (const float*)d_in[4];
    float* out = (float*)d_out;

    ln_x_kernel<<<RR, 128>>>(x);

    cudaFuncSetAttribute(gemm_proj_kernel,
                         cudaFuncAttributeMaxDynamicSharedMemorySize, G1_SMEM);
    dim3 g1(EE / 128, RR / 128);
    gemm_proj_kernel<<<g1, 256, G1_SMEM>>>(uvqk);

    cudaFuncSetAttribute(attn_kernel,
                         cudaFuncAttributeMaxDynamicSharedMemorySize,
                         ATT_SMEM_BYTES);
    dim3 ga(NN / 64, HH, BB);
    attn_kernel<<<ga, 256, ATT_SMEM_BYTES>>>();

    ln_attn_kernel<<<RR, 128>>>();

    cudaFuncSetAttribute(gemm_out_kernel,
                         cudaFuncAttributeMaxDynamicSharedMemorySize, G2_SMEM);
    dim3 g2(DD / 128, RR / 128);
    gemm_out_kernel<<<g2, 256, G2_SMEM>>>(o_w, o_b, x, out);
}

// round 8
// speedup vs baseline: 3.5968x; 1.6251x over previous
#include <cuda_runtime.h>
#include <cuda_fp16.h>
#include <math.h>
#include <stdint.h>

#define BB 4
#define NN 2048
#define DD 512
#define HH 8
#define RR (BB*NN)   // 8192 rows
#define EE 2048      // proj width

// ---------------- scratch (static device globals; no allocation) -------------
__device__ __half g_norm[(size_t)RR*DD];   // 8 MB   LN(x) fp16
__device__ __half g_proj[(size_t)RR*EE];   // 32 MB  silu(normX @ uvqk) fp16
__device__ float  g_attn[(size_t)RR*DD];   // 16 MB  attention output fp32
__device__ __half g_oin [(size_t)RR*DD];   // 8 MB   u * LN(attn) fp16
__device__ __half g_wh  [(size_t)EE*DD];   // 2 MB   uvqk^T fp16  [n][k]
__device__ __half g_woh [(size_t)DD*DD];   // 0.5 MB o_w fp16     [n][k]

__device__ __forceinline__ float silu_f(float v) { return v / (1.0f + __expf(-v)); }

// mma.sync m16n8k16 row.col f16 in, fp32 accumulate (in place)
__device__ __forceinline__ void mma16(float* d, uint32_t a0, uint32_t a1,
                                      uint32_t a2, uint32_t a3,
                                      uint32_t b0, uint32_t b1) {
    asm volatile(
        "mma.sync.aligned.m16n8k16.row.col.f32.f16.f16.f32 "
        "{%0,%1,%2,%3}, {%4,%5,%6,%7}, {%8,%9}, {%0,%1,%2,%3};"
        : "+f"(d[0]), "+f"(d[1]), "+f"(d[2]), "+f"(d[3])
        : "r"(a0), "r"(a1), "r"(a2), "r"(a3), "r"(b0), "r"(b1));
}

__device__ __forceinline__ uint32_t h2u(__half2 h) {
    return *(uint32_t*)&h;
}

__device__ __forceinline__ void cpa16(const void* dst_smem, const void* src) {
    uint32_t d = (uint32_t)__cvta_generic_to_shared(dst_smem);
    asm volatile("cp.async.cg.shared.global [%0], [%1], 16;\n" :: "r"(d), "l"(src));
}
#define CP_COMMIT() asm volatile("cp.async.commit_group;\n" ::: "memory")
#define CP_WAIT1()  asm volatile("cp.async.wait_group 1;\n" ::: "memory")
#define CP_WAIT0()  asm volatile("cp.async.wait_group 0;\n" ::: "memory")

// ---------------- weight conversion ------------------------------------------
// uvqk [DD][EE] fp32 -> g_wh [EE][DD] fp16 (transpose)
__global__ void cvt_uvqk_kernel(const float* __restrict__ W) {
    __shared__ float tile[32][33];
    int n0 = blockIdx.x * 32, k0 = blockIdx.y * 32;
    int tx = threadIdx.x, ty = threadIdx.y;   // 32 x 8
    #pragma unroll
    for (int j = 0; j < 4; j++)
        tile[ty + j * 8][tx] = W[(size_t)(k0 + ty + j * 8) * EE + n0 + tx];
    __syncthreads();
    #pragma unroll
    for (int j = 0; j < 4; j++)
        g_wh[(size_t)(n0 + ty + j * 8) * DD + k0 + tx] =
            __float2half(tile[tx][ty + j * 8]);
}

// o_w [DD][DD] fp32 -> fp16 direct (already [n][k])
__global__ void cvt_ow_kernel(const float* __restrict__ W) {
    int i = blockIdx.x * 256 + threadIdx.x;
    g_woh[i] = __float2half(W[i]);
}

// ---------------- LayerNorm of x -> g_norm (fp16)  ---------------------------
__global__ void ln_x_kernel(const float* __restrict__ x) {
    int row = blockIdx.x;
    int t = threadIdx.x;
    float4 v = ((const float4*)(x + (size_t)row * DD))[t];
    float s  = v.x + v.y + v.z + v.w;
    float ss = v.x*v.x + v.y*v.y + v.z*v.z + v.w*v.w;
    #pragma unroll
    for (int o = 16; o; o >>= 1) {
        s  += __shfl_xor_sync(0xffffffffu, s,  o);
        ss += __shfl_xor_sync(0xffffffffu, ss, o);
    }
    __shared__ float shs[4], shq[4];
    if ((t & 31) == 0) { shs[t >> 5] = s; shq[t >> 5] = ss; }
    __syncthreads();
    s  = shs[0] + shs[1] + shs[2] + shs[3];
    ss = shq[0] + shq[1] + shq[2] + shq[3];
    float mu  = s * (1.0f / DD);
    float var = ss * (1.0f / DD) - mu * mu;
    float rs  = rsqrtf(var + 1e-6f);
    __half2* op = (__half2*)(g_norm + (size_t)row * DD);
    op[2*t]   = __float22half2_rn(make_float2((v.x - mu) * rs, (v.y - mu) * rs));
    op[2*t+1] = __float22half2_rn(make_float2((v.z - mu) * rs, (v.w - mu) * rs));
}

// ============================================================================
// fp16 GEMM core layout: CTA 128x128xk32, 8 warps (2m x 4n), warp tile 64x32
// smem rows padded to LDA=40 halfs (80B) -> conflict-free b32 fragment loads
// ============================================================================
#define LDA 40
#define G_ASZ (128*LDA)                       // halfs per operand per stage
#define G_SMEM (4 * G_ASZ * (int)sizeof(__half))

// GEMM1: g_proj = silu(g_norm[8192x512] @ uvqk) ; B = g_wh [2048][512]
__global__ __launch_bounds__(256) void gemm_proj_kernel() {
    extern __shared__ __half smh[];
    __half* As[2] = { smh, smh + G_ASZ };
    __half* Bs[2] = { smh + 2*G_ASZ, smh + 3*G_ASZ };
    int bn = blockIdx.x * 128, bm = blockIdx.y * 128;
    int tid = threadIdx.x, lane = tid & 31, wid = tid >> 5;
    int g = lane >> 2, tig = lane & 3;
    int wm = wid >> 2, wn = wid & 3;
    float acc[4][4][4] = {};

    auto load_stage = [&](int s, int k0) {
        #pragma unroll
        for (int t = 0; t < 2; t++) {
            int idx = tid + t * 256;
            int r = idx >> 2, c = idx & 3;
            cpa16(As[s] + r * LDA + c * 8, g_norm + (size_t)(bm + r) * DD + k0 + c * 8);
            cpa16(Bs[s] + r * LDA + c * 8, g_wh   + (size_t)(bn + r) * DD + k0 + c * 8);
        }
        CP_COMMIT();
    };

    load_stage(0, 0);
    const int NK = DD / 32;
    for (int it = 0; it < NK; it++) {
        if (it + 1 < NK) { load_stage((it + 1) & 1, (it + 1) * 32); CP_WAIT1(); }
        else CP_WAIT0();
        __syncthreads();
        const __half* Ap = As[it & 1];
        const __half* Bp = Bs[it & 1];
        #pragma unroll
        for (int ks = 0; ks < 2; ks++) {
            int col = ks * 16 + 2 * tig;
            uint32_t af[4][4];
            #pragma unroll
            for (int mt = 0; mt < 4; mt++) {
                int r = wm * 64 + mt * 16 + g;
                af[mt][0] = *(const uint32_t*)(Ap + r * LDA + col);
                af[mt][1] = *(const uint32_t*)(Ap + (r + 8) * LDA + col);
                af[mt][2] = *(const uint32_t*)(Ap + r * LDA + col + 8);
                af[mt][3] = *(const uint32_t*)(Ap + (r + 8) * LDA + col + 8);
            }
            #pragma unroll
            for (int nt = 0; nt < 4; nt++) {
                int rn = wn * 32 + nt * 8 + g;
                uint32_t b0 = *(const uint32_t*)(Bp + rn * LDA + col);
                uint32_t b1 = *(const uint32_t*)(Bp + rn * LDA + col + 8);
                #pragma unroll
                for (int mt = 0; mt < 4; mt++)
                    mma16(acc[mt][nt], af[mt][0], af[mt][1], af[mt][2], af[mt][3], b0, b1);
            }
        }
        __syncthreads();
    }
    #pragma unroll
    for (int mt = 0; mt < 4; mt++) {
        int m0 = bm + wm * 64 + mt * 16 + g;
        #pragma unroll
        for (int nt = 0; nt < 4; nt++) {
            int n = bn + wn * 32 + nt * 8 + 2 * tig;
            *(__half2*)(g_proj + (size_t)m0 * EE + n) =
                __float22half2_rn(make_float2(silu_f(acc[mt][nt][0]), silu_f(acc[mt][nt][1])));
            *(__half2*)(g_proj + (size_t)(m0 + 8) * EE + n) =
                __float22half2_rn(make_float2(silu_f(acc[mt][nt][2]), silu_f(acc[mt][nt][3])));
        }
    }
}

// ============================================================================
// HSTU attention, fp16 mma, q-block 128, 8 warps; P register-resident.
// warp w owns q rows [16w, 16w+16); per 64-key tile: 32 QK mma + 32 PV mma.
// ============================================================================
#define LDH 72
#define ATT_SMEM_BYTES ((128 + 64 + 64) * LDH * (int)sizeof(__half))

__global__ __launch_bounds__(256) void attn_kernel() {
    extern __shared__ __half smh[];
    __half* Qs = smh;                 // [128][LDH] rows=q, cols=d
    __half* Ks = Qs + 128 * LDH;      // [64][LDH]  rows=m, cols=d
    __half* Vt = Ks + 64 * LDH;       // [64][LDH]  rows=d, cols=m
    int qbi = (int)(gridDim.x - 1 - blockIdx.x);   // big blocks first
    int h = blockIdx.y, b = blockIdx.z;
    int tid = threadIdx.x;
    int w = tid >> 5, lane = tid & 31, g = lane >> 2, tig = lane & 3;
    const __half* base = g_proj + (size_t)b * NN * EE;
    const __half* Qg = base + 1024 + h * 64;
    const __half* Kg = base + 1536 + h * 64;
    const __half* Vg = base + 512  + h * 64;
    int q0 = qbi * 128;
    int r0 = w * 16 + g;

    // load Q block: 128 rows x 8 int4 chunks
    #pragma unroll
    for (int t = 0; t < 4; t++) {
        int idx = tid + t * 256;
        int r = idx >> 3, c = idx & 7;
        *(int4*)(Qs + r * LDH + c * 8) =
            *(const int4*)(Qg + (size_t)(q0 + r) * EE + c * 8);
    }

    float oacc[8][4] = {};
    int ntile = 2 * qbi + 2;

    for (int mb = 0; mb < ntile; mb++) {
        int m0 = mb * 64;
        __syncthreads();
        #pragma unroll
        for (int t = 0; t < 2; t++) {
            int idx = tid + t * 256;
            int r = idx >> 3, c = idx & 7;
            *(int4*)(Ks + r * LDH + c * 8) =
                *(const int4*)(Kg + (size_t)(m0 + r) * EE + c * 8);
            int4 vv = *(const int4*)(Vg + (size_t)(m0 + r) * EE + c * 8);
            __half vh[8]; *(int4*)vh = vv;
            #pragma unroll
            for (int j = 0; j < 8; j++) Vt[(c * 8 + j) * LDH + r] = vh[j];
        }
        __syncthreads();

        if (m0 > q0 + w * 16 + 15) continue;   // warp fully masked (uniform)

        // Phase 1: S = Q K^T  (warp's 16 rows x 64 keys)
        float sacc[8][4] = {};
        #pragma unroll
        for (int kt = 0; kt < 4; kt++) {
            int col = kt * 16 + 2 * tig;
            uint32_t a0 = *(const uint32_t*)(Qs + r0 * LDH + col);
            uint32_t a1 = *(const uint32_t*)(Qs + (r0 + 8) * LDH + col);
            uint32_t a2 = *(const uint32_t*)(Qs + r0 * LDH + col + 8);
            uint32_t a3 = *(const uint32_t*)(Qs + (r0 + 8) * LDH + col + 8);
            #pragma unroll
            for (int nt = 0; nt < 8; nt++) {
                uint32_t b0 = *(const uint32_t*)(Ks + (nt * 8 + g) * LDH + col);
                uint32_t b1 = *(const uint32_t*)(Ks + (nt * 8 + g) * LDH + col + 8);
                mma16(sacc[nt], a0, a1, a2, a3, b0, b1);
            }
        }

        // silu + causal mask -> half2 (1/N deferred to epilogue); P stays in regs
        uint32_t ph[8][2];
        int gr0 = q0 + r0, gr1 = gr0 + 8;
        if (m0 + 63 > q0 + w * 16) {      // diagonal tile: element mask
            #pragma unroll
            for (int nt = 0; nt < 8; nt++) {
                int c0 = m0 + nt * 8 + 2 * tig, c1 = c0 + 1;
                float p0 = c0 <= gr0 ? silu_f(sacc[nt][0]) : 0.0f;
                float p1 = c1 <= gr0 ? silu_f(sacc[nt][1]) : 0.0f;
                float p2 = c0 <= gr1 ? silu_f(sacc[nt][2]) : 0.0f;
                float p3 = c1 <= gr1 ? silu_f(sacc[nt][3]) : 0.0f;
                ph[nt][0] = h2u(__float22half2_rn(make_float2(p0, p1)));
                ph[nt][1] = h2u(__float22half2_rn(make_float2(p2, p3)));
            }
        } else {
            #pragma unroll
            for (int nt = 0; nt < 8; nt++) {
                ph[nt][0] = h2u(__float22half2_rn(
                    make_float2(silu_f(sacc[nt][0]), silu_f(sacc[nt][1]))));
                ph[nt][1] = h2u(__float22half2_rn(
                    make_float2(silu_f(sacc[nt][2]), silu_f(sacc[nt][3]))));
            }
        }

        // Phase 2: O += P V   (P regs are already A-fragments)
        #pragma unroll
        for (int kt = 0; kt < 4; kt++) {
            uint32_t a0 = ph[2*kt][0], a1 = ph[2*kt][1];
            uint32_t a2 = ph[2*kt+1][0], a3 = ph[2*kt+1][1];
            int col = kt * 16 + 2 * tig;
            #pragma unroll
            for (int nt = 0; nt < 8; nt++) {
                uint32_t b0 = *(const uint32_t*)(Vt + (nt * 8 + g) * LDH + col);
                uint32_t b1 = *(const uint32_t*)(Vt + (nt * 8 + g) * LDH + col + 8);
                mma16(oacc[nt], a0, a1, a2, a3, b0, b1);
            }
        }
    }

    // store O (apply deferred 1/N)
    const float sc = 1.0f / NN;
    size_t row0 = (size_t)b * NN + q0 + r0;
    #pragma unroll
    for (int nt = 0; nt < 8; nt++) {
        int n = h * 64 + nt * 8 + 2 * tig;
        *(float2*)(g_attn + row0 * DD + n) =
            make_float2(oacc[nt][0] * sc, oacc[nt][1] * sc);
        *(float2*)(g_attn + (row0 + 8) * DD + n) =
            make_float2(oacc[nt][2] * sc, oacc[nt][3] * sc);
    }
}

// ---------------- LN(attn) * u -> g_oin (fp16) -------------------------------
__global__ void ln_attn_kernel() {
    int row = blockIdx.x;
    int t = threadIdx.x;
    float4 v = ((const float4*)(g_attn + (size_t)row * DD))[t];
    float s  = v.x + v.y + v.z + v.w;
    float ss = v.x*v.x + v.y*v.y + v.z*v.z + v.w*v.w;
    #pragma unroll
    for (int o = 16; o; o >>= 1) {
        s  += __shfl_xor_sync(0xffffffffu, s,  o);
        ss += __shfl_xor_sync(0xffffffffu, ss, o);
    }
    __shared__ float shs[4], shq[4];
    if ((t & 31) == 0) { shs[t >> 5] = s; shq[t >> 5] = ss; }
    __syncthreads();
    s  = shs[0] + shs[1] + shs[2] + shs[3];
    ss = shq[0] + shq[1] + shq[2] + shq[3];
    float mu  = s * (1.0f / DD);
    float var = ss * (1.0f / DD) - mu * mu;
    float rs  = rsqrtf(var + 1e-6f);
    const __half2* up = (const __half2*)(g_proj + (size_t)row * EE);
    float2 u0 = __half22float2(up[2*t]);
    float2 u1 = __half22float2(up[2*t+1]);
    __half2* op = (__half2*)(g_oin + (size_t)row * DD);
    op[2*t]   = __float22half2_rn(make_float2((v.x - mu) * rs * u0.x,
                                              (v.y - mu) * rs * u0.y));
    op[2*t+1] = __float22half2_rn(make_float2((v.z - mu) * rs * u1.x,
                                              (v.w - mu) * rs * u1.y));
}

// ============================================================================
// GEMM2: out = g_oin[8192x512] @ o_w^T + o_b + x  (fp32 out)
// ============================================================================
__global__ __launch_bounds__(256) void gemm_out_kernel(
    const float* __restrict__ bias, const float* __restrict__ x,
    float* __restrict__ out) {
    extern __shared__ __half smh[];
    __half* As[2] = { smh, smh + G_ASZ };
    __half* Bs[2] = { smh + 2*G_ASZ, smh + 3*G_ASZ };
    int bn = blockIdx.x * 128, bm = blockIdx.y * 128;
    int tid = threadIdx.x, lane = tid & 31, wid = tid >> 5;
    int g = lane >> 2, tig = lane & 3;
    int wm = wid >> 2, wn = wid & 3;
    float acc[4][4][4] = {};

    auto load_stage = [&](int s, int k0) {
        #pragma unroll
        for (int t = 0; t < 2; t++) {
            int idx = tid + t * 256;
            int r = idx >> 2, c = idx & 3;
            cpa16(As[s] + r * LDA + c * 8, g_oin + (size_t)(bm + r) * DD + k0 + c * 8);
            cpa16(Bs[s] + r * LDA + c * 8, g_woh + (size_t)(bn + r) * DD + k0 + c * 8);
        }
        CP_COMMIT();
    };

    load_stage(0, 0);
    const int NK = DD / 32;
    for (int it = 0; it < NK; it++) {
        if (it + 1 < NK) { load_stage((it + 1) & 1, (it + 1) * 32); CP_WAIT1(); }
        else CP_WAIT0();
        __syncthreads();
        const __half* Ap = As[it & 1];
        const __half* Bp = Bs[it & 1];
        #pragma unroll
        for (int ks = 0; ks < 2; ks++) {
            int col = ks * 16 + 2 * tig;
            uint32_t af[4][4];
            #pragma unroll
            for (int mt = 0; mt < 4; mt++) {
                int r = wm * 64 + mt * 16 + g;
                af[mt][0] = *(const uint32_t*)(Ap + r * LDA + col);
                af[mt][1] = *(const uint32_t*)(Ap + (r + 8) * LDA + col);
                af[mt][2] = *(const uint32_t*)(Ap + r * LDA + col + 8);
                af[mt][3] = *(const uint32_t*)(Ap + (r + 8) * LDA + col + 8);
            }
            #pragma unroll
            for (int nt = 0; nt < 4; nt++) {
                int rn = wn * 32 + nt * 8 + g;
                uint32_t b0 = *(const uint32_t*)(Bp + rn * LDA + col);
                uint32_t b1 = *(const uint32_t*)(Bp + rn * LDA + col + 8);
                #pragma unroll
                for (int mt = 0; mt < 4; mt++)
                    mma16(acc[mt][nt], af[mt][0], af[mt][1], af[mt][2], af[mt][3], b0, b1);
            }
        }
        __syncthreads();
    }
    #pragma unroll
    for (int mt = 0; mt < 4; mt++) {
        size_t m0 = (size_t)(bm + wm * 64 + mt * 16 + g);
        #pragma unroll
        for (int nt = 0; nt < 4; nt++) {
            int n = bn + wn * 32 + nt * 8 + 2 * tig;
            float2 b2 = *(const float2*)(bias + n);
            float2 x0 = *(const float2*)(x + m0 * DD + n);
            float2 x1 = *(const float2*)(x + (m0 + 8) * DD + n);
            *(float2*)(out + m0 * DD + n) =
                make_float2(acc[mt][nt][0] + b2.x + x0.x,
                            acc[mt][nt][1] + b2.y + x0.y);
            *(float2*)(out + (m0 + 8) * DD + n) =
                make_float2(acc[mt][nt][2] + b2.x + x1.x,
                            acc[mt][nt][3] + b2.y + x1.y);
        }
    }
}

// ---------------- launch -----------------------------------------------------
extern "C" void kernel_launch(void* const* d_in, const int* in_sizes, int n_in,
                              void* d_out, int out_size) {
    const float* x    = (const float*)d_in[0];
    // d_in[1] = invalid_attn_mask (tril causal) -- implemented analytically
    const float* uvqk = (const float*)d_in[2];
    const float* o_w  = (const float*)d_in[3];
    const float* o_b  = (const float*)d_in[4];
    float* out = (float*)d_out;

    ln_x_kernel<<<RR, 128>>>(x);

    dim3 gw(EE / 32, DD / 32);
    cvt_uvqk_kernel<<<gw, dim3(32, 8)>>>(uvqk);
    cvt_ow_kernel<<<(DD * DD) / 256, 256>>>(o_w);

    cudaFuncSetAttribute(gemm_proj_kernel,
                         cudaFuncAttributeMaxDynamicSharedMemorySize, G_SMEM);
    dim3 g1(EE / 128, RR / 128);
    gemm_proj_kernel<<<g1, 256, G_SMEM>>>();

    cudaFuncSetAttribute(attn_kernel,
                         cudaFuncAttributeMaxDynamicSharedMemorySize,
                         ATT_SMEM_BYTES);
    dim3 ga(NN / 128, HH, BB);
    attn_kernel<<<ga, 256, ATT_SMEM_BYTES>>>();

    ln_attn_kernel<<<RR, 128>>>();

    cudaFuncSetAttribute(gemm_out_kernel,
                         cudaFuncAttributeMaxDynamicSharedMemorySize, G_SMEM);
    dim3 g2(DD / 128, RR / 128);
    gemm_out_kernel<<<g2, 256, G_SMEM>>>(o_b, x, out);
}

// round 9
// speedup vs baseline: 4.4547x; 1.2385x over previous
#include <cuda_runtime.h>
#include <cuda_fp16.h>
#include <math.h>
#include <stdint.h>

#define BB 4
#define NN 2048
#define DD 512
#define HH 8
#define RR (BB*NN)   // 8192 rows
#define EE 2048      // proj width

// ---------------- scratch (static device globals; no allocation) -------------
__device__ __half g_norm[(size_t)RR*DD];   // 8 MB   LN(x) fp16
__device__ __half g_proj[(size_t)RR*EE];   // 32 MB  silu(normX @ uvqk) fp16
__device__ __half g_attn[(size_t)RR*DD];   // 8 MB   attention output fp16
__device__ __half g_oin [(size_t)RR*DD];   // 8 MB   u * LN(attn) fp16
__device__ __half g_wh  [(size_t)EE*DD];   // 2 MB   uvqk^T fp16  [n][k]
__device__ __half g_woh [(size_t)DD*DD];   // 0.5 MB o_w fp16     [n][k]

__device__ __forceinline__ float silu_f(float v) { return v / (1.0f + __expf(-v)); }

// mma.sync m16n8k16 row.col f16 in, fp32 accumulate (in place)
__device__ __forceinline__ void mma16(float* d, uint32_t a0, uint32_t a1,
                                      uint32_t a2, uint32_t a3,
                                      uint32_t b0, uint32_t b1) {
    asm volatile(
        "mma.sync.aligned.m16n8k16.row.col.f32.f16.f16.f32 "
        "{%0,%1,%2,%3}, {%4,%5,%6,%7}, {%8,%9}, {%0,%1,%2,%3};"
        : "+f"(d[0]), "+f"(d[1]), "+f"(d[2]), "+f"(d[3])
        : "r"(a0), "r"(a1), "r"(a2), "r"(a3), "r"(b0), "r"(b1));
}

__device__ __forceinline__ uint32_t h2u(__half2 h) { return *(uint32_t*)&h; }

__device__ __forceinline__ uint32_t smem_u32(const void* p) {
    return (uint32_t)__cvta_generic_to_shared(p);
}

__device__ __forceinline__ void ldmx4(uint32_t& r0, uint32_t& r1,
                                      uint32_t& r2, uint32_t& r3, uint32_t a) {
    asm volatile("ldmatrix.sync.aligned.m8n8.x4.shared.b16 {%0,%1,%2,%3}, [%4];"
        : "=r"(r0), "=r"(r1), "=r"(r2), "=r"(r3) : "r"(a));
}
__device__ __forceinline__ void ldmx4t(uint32_t& r0, uint32_t& r1,
                                       uint32_t& r2, uint32_t& r3, uint32_t a) {
    asm volatile("ldmatrix.sync.aligned.m8n8.x4.trans.shared.b16 {%0,%1,%2,%3}, [%4];"
        : "=r"(r0), "=r"(r1), "=r"(r2), "=r"(r3) : "r"(a));
}

__device__ __forceinline__ void cpa16(const void* dst_smem, const void* src) {
    uint32_t d = (uint32_t)__cvta_generic_to_shared(dst_smem);
    asm volatile("cp.async.cg.shared.global [%0], [%1], 16;\n" :: "r"(d), "l"(src));
}
#define CP_COMMIT() asm volatile("cp.async.commit_group;\n" ::: "memory")
#define CP_WAIT1()  asm volatile("cp.async.wait_group 1;\n" ::: "memory")
#define CP_WAIT0()  asm volatile("cp.async.wait_group 0;\n" ::: "memory")

// ---------------- weight conversion ------------------------------------------
__global__ void cvt_uvqk_kernel(const float* __restrict__ W) {
    __shared__ float tile[32][33];
    int n0 = blockIdx.x * 32, k0 = blockIdx.y * 32;
    int tx = threadIdx.x, ty = threadIdx.y;   // 32 x 8
    #pragma unroll
    for (int j = 0; j < 4; j++)
        tile[ty + j * 8][tx] = W[(size_t)(k0 + ty + j * 8) * EE + n0 + tx];
    __syncthreads();
    #pragma unroll
    for (int j = 0; j < 4; j++)
        g_wh[(size_t)(n0 + ty + j * 8) * DD + k0 + tx] =
            __float2half(tile[tx][ty + j * 8]);
}

__global__ void cvt_ow_kernel(const float* __restrict__ W) {
    int i = blockIdx.x * 256 + threadIdx.x;
    g_woh[i] = __float2half(W[i]);
}

// ---------------- LayerNorm of x -> g_norm (fp16)  ---------------------------
__global__ void ln_x_kernel(const float* __restrict__ x) {
    int row = blockIdx.x;
    int t = threadIdx.x;
    float4 v = ((const float4*)(x + (size_t)row * DD))[t];
    float s  = v.x + v.y + v.z + v.w;
    float ss = v.x*v.x + v.y*v.y + v.z*v.z + v.w*v.w;
    #pragma unroll
    for (int o = 16; o; o >>= 1) {
        s  += __shfl_xor_sync(0xffffffffu, s,  o);
        ss += __shfl_xor_sync(0xffffffffu, ss, o);
    }
    __shared__ float shs[4], shq[4];
    if ((t & 31) == 0) { shs[t >> 5] = s; shq[t >> 5] = ss; }
    __syncthreads();
    s  = shs[0] + shs[1] + shs[2] + shs[3];
    ss = shq[0] + shq[1] + shq[2] + shq[3];
    float mu  = s * (1.0f / DD);
    float var = ss * (1.0f / DD) - mu * mu;
    float rs  = rsqrtf(var + 1e-6f);
    __half2* op = (__half2*)(g_norm + (size_t)row * DD);
    op[2*t]   = __float22half2_rn(make_float2((v.x - mu) * rs, (v.y - mu) * rs));
    op[2*t+1] = __float22half2_rn(make_float2((v.z - mu) * rs, (v.w - mu) * rs));
}

// ============================================================================
// fp16 GEMM core: CTA 128x128xk32, 8 warps (2m x 4n), warp tile 64x32,
// ldmatrix fragment loads, cp.async 2-stage pipeline.  LDA=40 halfs.
// ============================================================================
#define LDA 40
#define G_ASZ (128*LDA)
#define G_SMEM (4 * G_ASZ * (int)sizeof(__half))

// GEMM1: g_proj = silu(g_norm[8192x512] @ uvqk) ; B = g_wh [2048][512]
__global__ __launch_bounds__(256) void gemm_proj_kernel() {
    extern __shared__ __half smh[];
    __half* As[2] = { smh, smh + G_ASZ };
    __half* Bs[2] = { smh + 2*G_ASZ, smh + 3*G_ASZ };
    int bn = blockIdx.x * 128, bm = blockIdx.y * 128;
    int tid = threadIdx.x, lane = tid & 31, wid = tid >> 5;
    int g = lane >> 2, tig = lane & 3;
    int wm = wid >> 2, wn = wid & 3;
    float acc[4][4][4] = {};

    // ldmatrix per-lane offsets (halfs)
    int a_off = (wm * 64 + (lane & 15)) * LDA + ((lane >> 4) << 3);
    int b_off = (wn * 32 + (lane & 7) + ((lane >> 4) << 3)) * LDA
              + (((lane >> 3) & 1) << 3);

    auto load_stage = [&](int s, int k0) {
        #pragma unroll
        for (int t = 0; t < 2; t++) {
            int idx = tid + t * 256;
            int r = idx >> 2, c = idx & 3;
            cpa16(As[s] + r * LDA + c * 8, g_norm + (size_t)(bm + r) * DD + k0 + c * 8);
            cpa16(Bs[s] + r * LDA + c * 8, g_wh   + (size_t)(bn + r) * DD + k0 + c * 8);
        }
        CP_COMMIT();
    };

    load_stage(0, 0);
    const int NK = DD / 32;
    for (int it = 0; it < NK; it++) {
        if (it + 1 < NK) { load_stage((it + 1) & 1, (it + 1) * 32); CP_WAIT1(); }
        else CP_WAIT0();
        __syncthreads();
        uint32_t abase = smem_u32(As[it & 1]) + a_off * 2;
        uint32_t bbase = smem_u32(Bs[it & 1]) + b_off * 2;
        #pragma unroll
        for (int ks = 0; ks < 2; ks++) {
            uint32_t af[4][4];
            #pragma unroll
            for (int mt = 0; mt < 4; mt++)
                ldmx4(af[mt][0], af[mt][1], af[mt][2], af[mt][3],
                      abase + (mt * 16 * LDA + ks * 16) * 2);
            #pragma unroll
            for (int p = 0; p < 2; p++) {
                uint32_t b0, b1, b2, b3;
                ldmx4(b0, b1, b2, b3, bbase + (p * 16 * LDA + ks * 16) * 2);
                #pragma unroll
                for (int mt = 0; mt < 4; mt++) {
                    mma16(acc[mt][2*p],   af[mt][0], af[mt][1], af[mt][2], af[mt][3], b0, b1);
                    mma16(acc[mt][2*p+1], af[mt][0], af[mt][1], af[mt][2], af[mt][3], b2, b3);
                }
            }
        }
        __syncthreads();
    }
    #pragma unroll
    for (int mt = 0; mt < 4; mt++) {
        int m0 = bm + wm * 64 + mt * 16 + g;
        #pragma unroll
        for (int nt = 0; nt < 4; nt++) {
            int n = bn + wn * 32 + nt * 8 + 2 * tig;
            *(__half2*)(g_proj + (size_t)m0 * EE + n) =
                __float22half2_rn(make_float2(silu_f(acc[mt][nt][0]), silu_f(acc[mt][nt][1])));
            *(__half2*)(g_proj + (size_t)(m0 + 8) * EE + n) =
                __float22half2_rn(make_float2(silu_f(acc[mt][nt][2]), silu_f(acc[mt][nt][3])));
        }
    }
}

// ============================================================================
// HSTU attention: q-block 128, 8 warps, P register-resident,
// cp.async double-buffered K/V tiles, ldmatrix (+.trans for V).
// ============================================================================
#define LDH 72
#define ATT_SMEM_BYTES ((128 + 4 * 64) * LDH * (int)sizeof(__half))

__global__ __launch_bounds__(256) void attn_kernel() {
    extern __shared__ __half smh[];
    __half* Qs = smh;                                   // [128][LDH]
    __half* Ksm[2] = { Qs + 128 * LDH, Qs + 128 * LDH + 64 * LDH };
    __half* Vsm[2] = { Qs + 128 * LDH + 2 * 64 * LDH,
                       Qs + 128 * LDH + 3 * 64 * LDH };
    int qbi = (int)(gridDim.x - 1 - blockIdx.x);        // big blocks first
    int h = blockIdx.y, b = blockIdx.z;
    int tid = threadIdx.x;
    int w = tid >> 5, lane = tid & 31, g = lane >> 2, tig = lane & 3;
    const __half* base = g_proj + (size_t)b * NN * EE;
    const __half* Qg = base + 1024 + h * 64;
    const __half* Kg = base + 1536 + h * 64;
    const __half* Vg = base + 512  + h * 64;
    int q0 = qbi * 128;
    int r0 = w * 16 + g;

    // ldmatrix per-lane offsets (halfs)
    int qa_off = (w * 16 + (lane & 15)) * LDH + ((lane >> 4) << 3);
    int kb_off = ((lane & 7) + ((lane >> 4) << 3)) * LDH + (((lane >> 3) & 1) << 3);
    int vb_off = ((lane & 7) + (((lane >> 3) & 1) << 3)) * LDH + ((lane >> 4) << 3);

    // load Q block
    #pragma unroll
    for (int t = 0; t < 4; t++) {
        int idx = tid + t * 256;
        int r = idx >> 3, c = idx & 7;
        *(int4*)(Qs + r * LDH + c * 8) =
            *(const int4*)(Qg + (size_t)(q0 + r) * EE + c * 8);
    }

    auto load_kv = [&](int s, int m0) {
        #pragma unroll
        for (int t = 0; t < 2; t++) {
            int idx = tid + t * 256;
            int r = idx >> 3, c = idx & 7;
            cpa16(Ksm[s] + r * LDH + c * 8, Kg + (size_t)(m0 + r) * EE + c * 8);
            cpa16(Vsm[s] + r * LDH + c * 8, Vg + (size_t)(m0 + r) * EE + c * 8);
        }
        CP_COMMIT();
    };

    float oacc[8][4] = {};
    int ntile = 2 * qbi + 2;
    load_kv(0, 0);

    for (int mb = 0; mb < ntile; mb++) {
        int m0 = mb * 64;
        if (mb + 1 < ntile) { load_kv((mb + 1) & 1, m0 + 64); CP_WAIT1(); }
        else CP_WAIT0();
        __syncthreads();

        if (m0 <= q0 + w * 16 + 15) {
            uint32_t qb32 = smem_u32(Qs) + qa_off * 2;
            uint32_t kb32 = smem_u32(Ksm[mb & 1]) + kb_off * 2;
            uint32_t vb32 = smem_u32(Vsm[mb & 1]) + vb_off * 2;

            // Phase 1: S = Q K^T
            float sacc[8][4] = {};
            #pragma unroll
            for (int kt = 0; kt < 4; kt++) {
                uint32_t a0, a1, a2, a3;
                ldmx4(a0, a1, a2, a3, qb32 + kt * 32);
                #pragma unroll
                for (int p = 0; p < 4; p++) {
                    uint32_t b0, b1, b2, b3;
                    ldmx4(b0, b1, b2, b3, kb32 + (p * 16 * LDH + kt * 16) * 2);
                    mma16(sacc[2*p],   a0, a1, a2, a3, b0, b1);
                    mma16(sacc[2*p+1], a0, a1, a2, a3, b2, b3);
                }
            }

            // silu + causal mask -> half2 (1/N deferred); P stays in regs
            uint32_t ph[8][2];
            int gr0 = q0 + r0, gr1 = gr0 + 8;
            if (m0 + 63 > q0 + w * 16) {      // diagonal tile
                #pragma unroll
                for (int nt = 0; nt < 8; nt++) {
                    int c0 = m0 + nt * 8 + 2 * tig, c1 = c0 + 1;
                    float p0 = c0 <= gr0 ? silu_f(sacc[nt][0]) : 0.0f;
                    float p1 = c1 <= gr0 ? silu_f(sacc[nt][1]) : 0.0f;
                    float p2 = c0 <= gr1 ? silu_f(sacc[nt][2]) : 0.0f;
                    float p3 = c1 <= gr1 ? silu_f(sacc[nt][3]) : 0.0f;
                    ph[nt][0] = h2u(__float22half2_rn(make_float2(p0, p1)));
                    ph[nt][1] = h2u(__float22half2_rn(make_float2(p2, p3)));
                }
            } else {
                #pragma unroll
                for (int nt = 0; nt < 8; nt++) {
                    ph[nt][0] = h2u(__float22half2_rn(
                        make_float2(silu_f(sacc[nt][0]), silu_f(sacc[nt][1]))));
                    ph[nt][1] = h2u(__float22half2_rn(
                        make_float2(silu_f(sacc[nt][2]), silu_f(sacc[nt][3]))));
                }
            }

            // Phase 2: O += P V  (V fragments via ldmatrix.trans)
            #pragma unroll
            for (int kt = 0; kt < 4; kt++) {
                uint32_t a0 = ph[2*kt][0], a1 = ph[2*kt][1];
                uint32_t a2 = ph[2*kt+1][0], a3 = ph[2*kt+1][1];
                #pragma unroll
                for (int p = 0; p < 4; p++) {
                    uint32_t b0, b1, b2, b3;
                    ldmx4t(b0, b1, b2, b3, vb32 + (kt * 16 * LDH + p * 16) * 2);
                    mma16(oacc[2*p],   a0, a1, a2, a3, b0, b1);
                    mma16(oacc[2*p+1], a0, a1, a2, a3, b2, b3);
                }
            }
        }
        __syncthreads();
    }

    // store O (fp16, apply deferred 1/N)
    const float sc = 1.0f / NN;
    size_t row0 = (size_t)b * NN + q0 + r0;
    #pragma unroll
    for (int nt = 0; nt < 8; nt++) {
        int n = h * 64 + nt * 8 + 2 * tig;
        *(__half2*)(g_attn + row0 * DD + n) =
            __float22half2_rn(make_float2(oacc[nt][0] * sc, oacc[nt][1] * sc));
        *(__half2*)(g_attn + (row0 + 8) * DD + n) =
            __float22half2_rn(make_float2(oacc[nt][2] * sc, oacc[nt][3] * sc));
    }
}

// ---------------- LN(attn fp16) * u -> g_oin (fp16) --------------------------
__global__ void ln_attn_kernel() {
    int row = blockIdx.x;
    int t = threadIdx.x;
    const __half2* ap = (const __half2*)(g_attn + (size_t)row * DD);
    float2 a0 = __half22float2(ap[2*t]);
    float2 a1 = __half22float2(ap[2*t+1]);
    float s  = a0.x + a0.y + a1.x + a1.y;
    float ss = a0.x*a0.x + a0.y*a0.y + a1.x*a1.x + a1.y*a1.y;
    #pragma unroll
    for (int o = 16; o; o >>= 1) {
        s  += __shfl_xor_sync(0xffffffffu, s,  o);
        ss += __shfl_xor_sync(0xffffffffu, ss, o);
    }
    __shared__ float shs[4], shq[4];
    if ((t & 31) == 0) { shs[t >> 5] = s; shq[t >> 5] = ss; }
    __syncthreads();
    s  = shs[0] + shs[1] + shs[2] + shs[3];
    ss = shq[0] + shq[1] + shq[2] + shq[3];
    float mu  = s * (1.0f / DD);
    float var = ss * (1.0f / DD) - mu * mu;
    float rs  = rsqrtf(var + 1e-6f);
    const __half2* up = (const __half2*)(g_proj + (size_t)row * EE);
    float2 u0 = __half22float2(up[2*t]);
    float2 u1 = __half22float2(up[2*t+1]);
    __half2* op = (__half2*)(g_oin + (size_t)row * DD);
    op[2*t]   = __float22half2_rn(make_float2((a0.x - mu) * rs * u0.x,
                                              (a0.y - mu) * rs * u0.y));
    op[2*t+1] = __float22half2_rn(make_float2((a1.x - mu) * rs * u1.x,
                                              (a1.y - mu) * rs * u1.y));
}

// ============================================================================
// GEMM2: out = g_oin[8192x512] @ o_w^T + o_b + x  (fp32 out)
// ============================================================================
__global__ __launch_bounds__(256) void gemm_out_kernel(
    const float* __restrict__ bias, const float* __restrict__ x,
    float* __restrict__ out) {
    extern __shared__ __half smh[];
    __half* As[2] = { smh, smh + G_ASZ };
    __half* Bs[2] = { smh + 2*G_ASZ, smh + 3*G_ASZ };
    int bn = blockIdx.x * 128, bm = blockIdx.y * 128;
    int tid = threadIdx.x, lane = tid & 31, wid = tid >> 5;
    int g = lane >> 2, tig = lane & 3;
    int wm = wid >> 2, wn = wid & 3;
    float acc[4][4][4] = {};

    int a_off = (wm * 64 + (lane & 15)) * LDA + ((lane >> 4) << 3);
    int b_off = (wn * 32 + (lane & 7) + ((lane >> 4) << 3)) * LDA
              + (((lane >> 3) & 1) << 3);

    auto load_stage = [&](int s, int k0) {
        #pragma unroll
        for (int t = 0; t < 2; t++) {
            int idx = tid + t * 256;
            int r = idx >> 2, c = idx & 3;
            cpa16(As[s] + r * LDA + c * 8, g_oin + (size_t)(bm + r) * DD + k0 + c * 8);
            cpa16(Bs[s] + r * LDA + c * 8, g_woh + (size_t)(bn + r) * DD + k0 + c * 8);
        }
        CP_COMMIT();
    };

    load_stage(0, 0);
    const int NK = DD / 32;
    for (int it = 0; it < NK; it++) {
        if (it + 1 < NK) { load_stage((it + 1) & 1, (it + 1) * 32); CP_WAIT1(); }
        else CP_WAIT0();
        __syncthreads();
        uint32_t abase = smem_u32(As[it & 1]) + a_off * 2;
        uint32_t bbase = smem_u32(Bs[it & 1]) + b_off * 2;
        #pragma unroll
        for (int ks = 0; ks < 2; ks++) {
            uint32_t af[4][4];
            #pragma unroll
            for (int mt = 0; mt < 4; mt++)
                ldmx4(af[mt][0], af[mt][1], af[mt][2], af[mt][3],
                      abase + (mt * 16 * LDA + ks * 16) * 2);
            #pragma unroll
            for (int p = 0; p < 2; p++) {
                uint32_t b0, b1, b2, b3;
                ldmx4(b0, b1, b2, b3, bbase + (p * 16 * LDA + ks * 16) * 2);
                #pragma unroll
                for (int mt = 0; mt < 4; mt++) {
                    mma16(acc[mt][2*p],   af[mt][0], af[mt][1], af[mt][2], af[mt][3], b0, b1);
                    mma16(acc[mt][2*p+1], af[mt][0], af[mt][1], af[mt][2], af[mt][3], b2, b3);
                }
            }
        }
        __syncthreads();
    }
    #pragma unroll
    for (int mt = 0; mt < 4; mt++) {
        size_t m0 = (size_t)(bm + wm * 64 + mt * 16 + g);
        #pragma unroll
        for (int nt = 0; nt < 4; nt++) {
            int n = bn + wn * 32 + nt * 8 + 2 * tig;
            float2 b2 = *(const float2*)(bias + n);
            float2 x0 = *(const float2*)(x + m0 * DD + n);
            float2 x1 = *(const float2*)(x + (m0 + 8) * DD + n);
            *(float2*)(out + m0 * DD + n) =
                make_float2(acc[mt][nt][0] + b2.x + x0.x,
                            acc[mt][nt][1] + b2.y + x0.y);
            *(float2*)(out + (m0 + 8) * DD + n) =
                make_float2(acc[mt][nt][2] + b2.x + x1.x,
                            acc[mt][nt][3] + b2.y + x1.y);
        }
    }
}

// ---------------- launch -----------------------------------------------------
extern "C" void kernel_launch(void* const* d_in, const int* in_sizes, int n_in,
                              void* d_out, int out_size) {
    const float* x    = (const float*)d_in[0];
    // d_in[1] = invalid_attn_mask (tril causal) -- implemented analytically
    const float* uvqk = (const float*)d_in[2];
    const float* o_w  = (const float*)d_in[3];
    const float* o_b  = (const float*)d_in[4];
    float* out = (float*)d_out;

    ln_x_kernel<<<RR, 128>>>(x);

    dim3 gw(EE / 32, DD / 32);
    cvt_uvqk_kernel<<<gw, dim3(32, 8)>>>(uvqk);
    cvt_ow_kernel<<<(DD * DD) / 256, 256>>>(o_w);

    cudaFuncSetAttribute(gemm_proj_kernel,
                         cudaFuncAttributeMaxDynamicSharedMemorySize, G_SMEM);
    dim3 g1(EE / 128, RR / 128);
    gemm_proj_kernel<<<g1, 256, G_SMEM>>>();

    cudaFuncSetAttribute(attn_kernel,
                         cudaFuncAttributeMaxDynamicSharedMemorySize,
                         ATT_SMEM_BYTES);
    dim3 ga(NN / 128, HH, BB);
    attn_kernel<<<ga, 256, ATT_SMEM_BYTES>>>();

    ln_attn_kernel<<<RR, 128>>>();

    cudaFuncSetAttribute(gemm_out_kernel,
                         cudaFuncAttributeMaxDynamicSharedMemorySize, G_SMEM);
    dim3 g2(DD / 128, RR / 128);
    gemm_out_kernel<<<g2, 256, G_SMEM>>>(o_b, x, out);
}

// round 11
// speedup vs baseline: 6.0293x; 1.3535x over previous
#include <cuda_runtime.h>
#include <cuda_fp16.h>
#include <math.h>
#include <stdint.h>

#define BB 4
#define NN 2048
#define DD 512
#define HH 8
#define RR (BB*NN)   // 8192 rows
#define EE 2048      // proj width

// ---------------- scratch (static device globals; no allocation) -------------
__device__ __half g_norm[(size_t)RR*DD];   // 8 MB   LN(x) fp16
__device__ __half g_proj[(size_t)RR*EE];   // 32 MB  silu(normX @ uvqk) fp16
__device__ __half g_attn[(size_t)RR*DD];   // 8 MB   attention output fp16
__device__ __half g_oin [(size_t)RR*DD];   // 8 MB   u * LN(attn) fp16
__device__ __half g_wh  [(size_t)EE*DD];   // 2 MB   uvqk^T fp16  [n][k]
__device__ __half g_woh [(size_t)DD*DD];   // 0.5 MB o_w fp16     [n][k]

__device__ __forceinline__ float silu_f(float v) { return v / (1.0f + __expf(-v)); }

// fast fp16x2 silu: 0.5*s*(1+tanh(0.5*s)) — one MUFU per two elements
__device__ __forceinline__ uint32_t silu2u(uint32_t s) {
    uint32_t p;
    asm("{\n\t.reg .b32 hs, th;\n\t"
        "mul.f16x2 hs, %1, %2;\n\t"
        "tanh.approx.f16x2 th, hs;\n\t"
        "add.f16x2 th, th, %3;\n\t"
        "mul.f16x2 %0, hs, th;\n\t}"
        : "=r"(p) : "r"(s), "r"(0x38003800u), "r"(0x3C003C00u));
    return p;
}

// mma.sync m16n8k16 row.col f16 in, fp32 accumulate (in place)
__device__ __forceinline__ void mma16(float* d, uint32_t a0, uint32_t a1,
                                      uint32_t a2, uint32_t a3,
                                      uint32_t b0, uint32_t b1) {
    asm volatile(
        "mma.sync.aligned.m16n8k16.row.col.f32.f16.f16.f32 "
        "{%0,%1,%2,%3}, {%4,%5,%6,%7}, {%8,%9}, {%0,%1,%2,%3};"
        : "+f"(d[0]), "+f"(d[1]), "+f"(d[2]), "+f"(d[3])
        : "r"(a0), "r"(a1), "r"(a2), "r"(a3), "r"(b0), "r"(b1));
}

__device__ __forceinline__ uint32_t h2u(__half2 h) { return *(uint32_t*)&h; }

__device__ __forceinline__ uint32_t smem_u32(const void* p) {
    return (uint32_t)__cvta_generic_to_shared(p);
}

__device__ __forceinline__ void ldmx4(uint32_t& r0, uint32_t& r1,
                                      uint32_t& r2, uint32_t& r3, uint32_t a) {
    asm volatile("ldmatrix.sync.aligned.m8n8.x4.shared.b16 {%0,%1,%2,%3}, [%4];"
        : "=r"(r0), "=r"(r1), "=r"(r2), "=r"(r3) : "r"(a));
}
__device__ __forceinline__ void ldmx4t(uint32_t& r0, uint32_t& r1,
                                       uint32_t& r2, uint32_t& r3, uint32_t a) {
    asm volatile("ldmatrix.sync.aligned.m8n8.x4.trans.shared.b16 {%0,%1,%2,%3}, [%4];"
        : "=r"(r0), "=r"(r1), "=r"(r2), "=r"(r3) : "r"(a));
}

__device__ __forceinline__ void cpa16(const void* dst_smem, const void* src) {
    uint32_t d = (uint32_t)__cvta_generic_to_shared(dst_smem);
    asm volatile("cp.async.cg.shared.global [%0], [%1], 16;\n" :: "r"(d), "l"(src));
}
#define CP_COMMIT() asm volatile("cp.async.commit_group;\n" ::: "memory")
#define CP_WAIT2()  asm volatile("cp.async.wait_group 2;\n" ::: "memory")
#define CP_WAIT1()  asm volatile("cp.async.wait_group 1;\n" ::: "memory")
#define CP_WAIT0()  asm volatile("cp.async.wait_group 0;\n" ::: "memory")

// ---------------- weight conversion ------------------------------------------
__global__ void cvt_uvqk_kernel(const float* __restrict__ W) {
    __shared__ float tile[32][33];
    int n0 = blockIdx.x * 32, k0 = blockIdx.y * 32;
    int tx = threadIdx.x, ty = threadIdx.y;   // 32 x 8
    #pragma unroll
    for (int j = 0; j < 4; j++)
        tile[ty + j * 8][tx] = W[(size_t)(k0 + ty + j * 8) * EE + n0 + tx];
    __syncthreads();
    #pragma unroll
    for (int j = 0; j < 4; j++)
        g_wh[(size_t)(n0 + ty + j * 8) * DD + k0 + tx] =
            __float2half(tile[tx][ty + j * 8]);
}

__global__ void cvt_ow_kernel(const float* __restrict__ W) {
    int i = blockIdx.x * 256 + threadIdx.x;
    g_woh[i] = __float2half(W[i]);
}

// ---------------- LayerNorm of x -> g_norm (fp16)  ---------------------------
__global__ void ln_x_kernel(const float* __restrict__ x) {
    int row = blockIdx.x;
    int t = threadIdx.x;
    float4 v = ((const float4*)(x + (size_t)row * DD))[t];
    float s  = v.x + v.y + v.z + v.w;
    float ss = v.x*v.x + v.y*v.y + v.z*v.z + v.w*v.w;
    #pragma unroll
    for (int o = 16; o; o >>= 1) {
        s  += __shfl_xor_sync(0xffffffffu, s,  o);
        ss += __shfl_xor_sync(0xffffffffu, ss, o);
    }
    __shared__ float shs[4], shq[4];
    if ((t & 31) == 0) { shs[t >> 5] = s; shq[t >> 5] = ss; }
    __syncthreads();
    s  = shs[0] + shs[1] + shs[2] + shs[3];
    ss = shq[0] + shq[1] + shq[2] + shq[3];
    float mu  = s * (1.0f / DD);
    float var = ss * (1.0f / DD) - mu * mu;
    float rs  = rsqrtf(var + 1e-6f);
    __half2* op = (__half2*)(g_norm + (size_t)row * DD);
    op[2*t]   = __float22half2_rn(make_float2((v.x - mu) * rs, (v.y - mu) * rs));
    op[2*t+1] = __float22half2_rn(make_float2((v.z - mu) * rs, (v.w - mu) * rs));
}

// ============================================================================
// fp16 GEMM core: CTA 128x128xk32, 8 warps (2m x 4n), warp tile 64x32,
// ldmatrix fragments, cp.async 4-stage pipeline, ONE barrier per k-iter.
// LDA=40 halfs.
// ============================================================================
#define LDA 40
#define G_ASZ (128*LDA)
#define G_SMEM (8 * G_ASZ * (int)sizeof(__half))   // 4 stages x (A+B)

// GEMM1: g_proj = silu(g_norm[8192x512] @ uvqk) ; B = g_wh [2048][512]
__global__ __launch_bounds__(256) void gemm_proj_kernel() {
    extern __shared__ __half smh[];
    __half* As[4] = { smh, smh + G_ASZ, smh + 2*G_ASZ, smh + 3*G_ASZ };
    __half* Bs[4] = { smh + 4*G_ASZ, smh + 5*G_ASZ, smh + 6*G_ASZ, smh + 7*G_ASZ };
    int bn = blockIdx.x * 128, bm = blockIdx.y * 128;
    int tid = threadIdx.x, lane = tid & 31, wid = tid >> 5;
    int g = lane >> 2, tig = lane & 3;
    int wm = wid >> 2, wn = wid & 3;
    float acc[4][4][4] = {};

    int a_off = (wm * 64 + (lane & 15)) * LDA + ((lane >> 4) << 3);
    int b_off = (wn * 32 + (lane & 7) + ((lane >> 4) << 3)) * LDA
              + (((lane >> 3) & 1) << 3);

    auto load_stage = [&](int s, int k0) {
        #pragma unroll
        for (int t = 0; t < 2; t++) {
            int idx = tid + t * 256;
            int r = idx >> 2, c = idx & 3;
            cpa16(As[s] + r * LDA + c * 8, g_norm + (size_t)(bm + r) * DD + k0 + c * 8);
            cpa16(Bs[s] + r * LDA + c * 8, g_wh   + (size_t)(bn + r) * DD + k0 + c * 8);
        }
    };

    #pragma unroll
    for (int s = 0; s < 3; s++) { load_stage(s, s * 32); CP_COMMIT(); }
    const int NK = DD / 32;   // 16
    for (int it = 0; it < NK; it++) {
        CP_WAIT2();
        __syncthreads();
        uint32_t abase = smem_u32(As[it & 3]) + a_off * 2;
        uint32_t bbase = smem_u32(Bs[it & 3]) + b_off * 2;
        #pragma unroll
        for (int ks = 0; ks < 2; ks++) {
            uint32_t af[4][4];
            #pragma unroll
            for (int mt = 0; mt < 4; mt++)
                ldmx4(af[mt][0], af[mt][1], af[mt][2], af[mt][3],
                      abase + (mt * 16 * LDA + ks * 16) * 2);
            #pragma unroll
            for (int p = 0; p < 2; p++) {
                uint32_t b0, b1, b2, b3;
                ldmx4(b0, b1, b2, b3, bbase + (p * 16 * LDA + ks * 16) * 2);
                #pragma unroll
                for (int mt = 0; mt < 4; mt++) {
                    mma16(acc[mt][2*p],   af[mt][0], af[mt][1], af[mt][2], af[mt][3], b0, b1);
                    mma16(acc[mt][2*p+1], af[mt][0], af[mt][1], af[mt][2], af[mt][3], b2, b3);
                }
            }
        }
        if (it + 3 < NK) load_stage((it + 3) & 3, (it + 3) * 32);
        CP_COMMIT();   // unconditional: keeps group accounting uniform
    }
    #pragma unroll
    for (int mt = 0; mt < 4; mt++) {
        int m0 = bm + wm * 64 + mt * 16 + g;
        #pragma unroll
        for (int nt = 0; nt < 4; nt++) {
            int n = bn + wn * 32 + nt * 8 + 2 * tig;
            *(__half2*)(g_proj + (size_t)m0 * EE + n) =
                __float22half2_rn(make_float2(silu_f(acc[mt][nt][0]), silu_f(acc[mt][nt][1])));
            *(__half2*)(g_proj + (size_t)(m0 + 8) * EE + n) =
                __float22half2_rn(make_float2(silu_f(acc[mt][nt][2]), silu_f(acc[mt][nt][3])));
        }
    }
}

// ============================================================================
// HSTU attention: q-block 128, 8 warps, P register-resident,
// cp.async double-buffered K/V, ldmatrix (+.trans for V),
// fast f16x2 tanh-silu on full tiles.
// ============================================================================
#define LDH 72
#define ATT_SMEM_BYTES ((128 + 4 * 64) * LDH * (int)sizeof(__half))

__global__ __launch_bounds__(256) void attn_kernel() {
    extern __shared__ __half smh[];
    __half* Qs = smh;
    __half* Ksm[2] = { Qs + 128 * LDH, Qs + 128 * LDH + 64 * LDH };
    __half* Vsm[2] = { Qs + 128 * LDH + 2 * 64 * LDH,
                       Qs + 128 * LDH + 3 * 64 * LDH };
    int qbi = (int)(gridDim.x - 1 - blockIdx.x);
    int h = blockIdx.y, b = blockIdx.z;
    int tid = threadIdx.x;
    int w = tid >> 5, lane = tid & 31, g = lane >> 2, tig = lane & 3;
    const __half* base = g_proj + (size_t)b * NN * EE;
    const __half* Qg = base + 1024 + h * 64;
    const __half* Kg = base + 1536 + h * 64;
    const __half* Vg = base + 512  + h * 64;
    int q0 = qbi * 128;
    int r0 = w * 16 + g;

    int qa_off = (w * 16 + (lane & 15)) * LDH + ((lane >> 4) << 3);
    int kb_off = ((lane & 7) + ((lane >> 4) << 3)) * LDH + (((lane >> 3) & 1) << 3);
    int vb_off = ((lane & 7) + (((lane >> 3) & 1) << 3)) * LDH + ((lane >> 4) << 3);

    #pragma unroll
    for (int t = 0; t < 4; t++) {
        int idx = tid + t * 256;
        int r = idx >> 3, c = idx & 7;
        *(int4*)(Qs + r * LDH + c * 8) =
            *(const int4*)(Qg + (size_t)(q0 + r) * EE + c * 8);
    }

    auto load_kv = [&](int s, int m0) {
        #pragma unroll
        for (int t = 0; t < 2; t++) {
            int idx = tid + t * 256;
            int r = idx >> 3, c = idx & 7;
            cpa16(Ksm[s] + r * LDH + c * 8, Kg + (size_t)(m0 + r) * EE + c * 8);
            cpa16(Vsm[s] + r * LDH + c * 8, Vg + (size_t)(m0 + r) * EE + c * 8);
        }
        CP_COMMIT();
    };

    float oacc[8][4] = {};
    int ntile = 2 * qbi + 2;
    load_kv(0, 0);

    for (int mb = 0; mb < ntile; mb++) {
        int m0 = mb * 64;
        if (mb + 1 < ntile) { load_kv((mb + 1) & 1, m0 + 64); CP_WAIT1(); }
        else CP_WAIT0();
        __syncthreads();

        if (m0 <= q0 + w * 16 + 15) {
            uint32_t qb32 = smem_u32(Qs) + qa_off * 2;
            uint32_t kb32 = smem_u32(Ksm[mb & 1]) + kb_off * 2;
            uint32_t vb32 = smem_u32(Vsm[mb & 1]) + vb_off * 2;

            float sacc[8][4] = {};
            #pragma unroll
            for (int kt = 0; kt < 4; kt++) {
                uint32_t a0, a1, a2, a3;
                ldmx4(a0, a1, a2, a3, qb32 + kt * 32);
                #pragma unroll
                for (int p = 0; p < 4; p++) {
                    uint32_t b0, b1, b2, b3;
                    ldmx4(b0, b1, b2, b3, kb32 + (p * 16 * LDH + kt * 16) * 2);
                    mma16(sacc[2*p],   a0, a1, a2, a3, b0, b1);
                    mma16(sacc[2*p+1], a0, a1, a2, a3, b2, b3);
                }
            }

            uint32_t ph[8][2];
            int gr0 = q0 + r0, gr1 = gr0 + 8;
            if (m0 + 63 > q0 + w * 16) {      // diagonal tile: exact fp32 + mask
                #pragma unroll
                for (int nt = 0; nt < 8; nt++) {
                    int c0 = m0 + nt * 8 + 2 * tig, c1 = c0 + 1;
                    float p0 = c0 <= gr0 ? silu_f(sacc[nt][0]) : 0.0f;
                    float p1 = c1 <= gr0 ? silu_f(sacc[nt][1]) : 0.0f;
                    float p2 = c0 <= gr1 ? silu_f(sacc[nt][2]) : 0.0f;
                    float p3 = c1 <= gr1 ? silu_f(sacc[nt][3]) : 0.0f;
                    ph[nt][0] = h2u(__float22half2_rn(make_float2(p0, p1)));
                    ph[nt][1] = h2u(__float22half2_rn(make_float2(p2, p3)));
                }
            } else {                           // full tile: f16x2 tanh silu
                #pragma unroll
                for (int nt = 0; nt < 8; nt++) {
                    ph[nt][0] = silu2u(h2u(__float22half2_rn(
                        make_float2(sacc[nt][0], sacc[nt][1]))));
                    ph[nt][1] = silu2u(h2u(__float22half2_rn(
                        make_float2(sacc[nt][2], sacc[nt][3]))));
                }
            }

            #pragma unroll
            for (int kt = 0; kt < 4; kt++) {
                uint32_t a0 = ph[2*kt][0], a1 = ph[2*kt][1];
                uint32_t a2 = ph[2*kt+1][0], a3 = ph[2*kt+1][1];
                #pragma unroll
                for (int p = 0; p < 4; p++) {
                    uint32_t b0, b1, b2, b3;
                    ldmx4t(b0, b1, b2, b3, vb32 + (kt * 16 * LDH + p * 16) * 2);
                    mma16(oacc[2*p],   a0, a1, a2, a3, b0, b1);
                    mma16(oacc[2*p+1], a0, a1, a2, a3, b2, b3);
                }
            }
        }
        __syncthreads();
    }

    const float sc = 1.0f / NN;
    size_t row0 = (size_t)b * NN + q0 + r0;
    #pragma unroll
    for (int nt = 0; nt < 8; nt++) {
        int n = h * 64 + nt * 8 + 2 * tig;
        *(__half2*)(g_attn + row0 * DD + n) =
            __float22half2_rn(make_float2(oacc[nt][0] * sc, oacc[nt][1] * sc));
        *(__half2*)(g_attn + (row0 + 8) * DD + n) =
            __float22half2_rn(make_float2(oacc[nt][2] * sc, oacc[nt][3] * sc));
    }
}

// ---------------- LN(attn fp16) * u -> g_oin (fp16) --------------------------
__global__ void ln_attn_kernel() {
    int row = blockIdx.x;
    int t = threadIdx.x;
    const __half2* ap = (const __half2*)(g_attn + (size_t)row * DD);
    float2 a0 = __half22float2(ap[2*t]);
    float2 a1 = __half22float2(ap[2*t+1]);
    float s  = a0.x + a0.y + a1.x + a1.y;
    float ss = a0.x*a0.x + a0.y*a0.y + a1.x*a1.x + a1.y*a1.y;
    #pragma unroll
    for (int o = 16; o; o >>= 1) {
        s  += __shfl_xor_sync(0xffffffffu, s,  o);
        ss += __shfl_xor_sync(0xffffffffu, ss, o);
    }
    __shared__ float shs[4], shq[4];
    if ((t & 31) == 0) { shs[t >> 5] = s; shq[t >> 5] = ss; }
    __syncthreads();
    s  = shs[0] + shs[1] + shs[2] + shs[3];
    ss = shq[0] + shq[1] + shq[2] + shq[3];
    float mu  = s * (1.0f / DD);
    float var = ss * (1.0f / DD) - mu * mu;
    float rs  = rsqrtf(var + 1e-6f);
    const __half2* up = (const __half2*)(g_proj + (size_t)row * EE);
    float2 u0 = __half22float2(up[2*t]);
    float2 u1 = __half22float2(up[2*t+1]);
    __half2* op = (__half2*)(g_oin + (size_t)row * DD);
    op[2*t]   = __float22half2_rn(make_float2((a0.x - mu) * rs * u0.x,
                                              (a0.y - mu) * rs * u0.y));
    op[2*t+1] = __float22half2_rn(make_float2((a1.x - mu) * rs * u1.x,
                                              (a1.y - mu) * rs * u1.y));
}

// ============================================================================
// GEMM2: out = g_oin[8192x512] @ o_w^T + o_b + x  (fp32 out)
// ============================================================================
__global__ __launch_bounds__(256) void gemm_out_kernel(
    const float* __restrict__ bias, const float* __restrict__ x,
    float* __restrict__ out) {
    extern __shared__ __half smh[];
    __half* As[4] = { smh, smh + G_ASZ, smh + 2*G_ASZ, smh + 3*G_ASZ };
    __half* Bs[4] = { smh + 4*G_ASZ, smh + 5*G_ASZ, smh + 6*G_ASZ, smh + 7*G_ASZ };
    int bn = blockIdx.x * 128, bm = blockIdx.y * 128;
    int tid = threadIdx.x, lane = tid & 31, wid = tid >> 5;
    int g = lane >> 2, tig = lane & 3;
    int wm = wid >> 2, wn = wid & 3;
    float acc[4][4][4] = {};

    int a_off = (wm * 64 + (lane & 15)) * LDA + ((lane >> 4) << 3);
    int b_off = (wn * 32 + (lane & 7) + ((lane >> 4) << 3)) * LDA
              + (((lane >> 3) & 1) << 3);

    auto load_stage = [&](int s, int k0) {
        #pragma unroll
        for (int t = 0; t < 2; t++) {
            int idx = tid + t * 256;
            int r = idx >> 2, c = idx & 3;
            cpa16(As[s] + r * LDA + c * 8, g_oin + (size_t)(bm + r) * DD + k0 + c * 8);
            cpa16(Bs[s] + r * LDA + c * 8, g_woh + (size_t)(bn + r) * DD + k0 + c * 8);
        }
    };

    #pragma unroll
    for (int s = 0; s < 3; s++) { load_stage(s, s * 32); CP_COMMIT(); }
    const int NK = DD / 32;
    for (int it = 0; it < NK; it++) {
        CP_WAIT2();
        __syncthreads();
        uint32_t abase = smem_u32(As[it & 3]) + a_off * 2;
        uint32_t bbase = smem_u32(Bs[it & 3]) + b_off * 2;
        #pragma unroll
        for (int ks = 0; ks < 2; ks++) {
            uint32_t af[4][4];
            #pragma unroll
            for (int mt = 0; mt < 4; mt++)
                ldmx4(af[mt][0], af[mt][1], af[mt][2], af[mt][3],
                      abase + (mt * 16 * LDA + ks * 16) * 2);
            #pragma unroll
            for (int p = 0; p < 2; p++) {
                uint32_t b0, b1, b2, b3;
                ldmx4(b0, b1, b2, b3, bbase + (p * 16 * LDA + ks * 16) * 2);
                #pragma unroll
                for (int mt = 0; mt < 4; mt++) {
                    mma16(acc[mt][2*p],   af[mt][0], af[mt][1], af[mt][2], af[mt][3], b0, b1);
                    mma16(acc[mt][2*p+1], af[mt][0], af[mt][1], af[mt][2], af[mt][3], b2, b3);
                }
            }
        }
        if (it + 3 < NK) load_stage((it + 3) & 3, (it + 3) * 32);
        CP_COMMIT();
    }
    #pragma unroll
    for (int mt = 0; mt < 4; mt++) {
        size_t m0 = (size_t)(bm + wm * 64 + mt * 16 + g);
        #pragma unroll
        for (int nt = 0; nt < 4; nt++) {
            int n = bn + wn * 32 + nt * 8 + 2 * tig;
            float2 b2 = *(const float2*)(bias + n);
            float2 x0 = *(const float2*)(x + m0 * DD + n);
            float2 x1 = *(const float2*)(x + (m0 + 8) * DD + n);
            *(float2*)(out + m0 * DD + n) =
                make_float2(acc[mt][nt][0] + b2.x + x0.x,
                            acc[mt][nt][1] + b2.y + x0.y);
            *(float2*)(out + (m0 + 8) * DD + n) =
                make_float2(acc[mt][nt][2] + b2.x + x1.x,
                            acc[mt][nt][3] + b2.y + x1.y);
        }
    }
}

// ---------------- launch -----------------------------------------------------
extern "C" void kernel_launch(void* const* d_in, const int* in_sizes, int n_in,
                              void* d_out, int out_size) {
    const float* x    = (const float*)d_in[0];
    // d_in[1] = invalid_attn_mask (tril causal) -- implemented analytically
    const float* uvqk = (const float*)d_in[2];
    const float* o_w  = (const float*)d_in[3];
    const float* o_b  = (const float*)d_in[4];
    float* out = (float*)d_out;

    ln_x_kernel<<<RR, 128>>>(x);

    dim3 gw(EE / 32, DD / 32);
    cvt_uvqk_kernel<<<gw, dim3(32, 8)>>>(uvqk);
    cvt_ow_kernel<<<(DD * DD) / 256, 256>>>(o_w);

    cudaFuncSetAttribute(gemm_proj_kernel,
                         cudaFuncAttributeMaxDynamicSharedMemorySize, G_SMEM);
    dim3 g1(EE / 128, RR / 128);
    gemm_proj_kernel<<<g1, 256, G_SMEM>>>();

    cudaFuncSetAttribute(attn_kernel,
                         cudaFuncAttributeMaxDynamicSharedMemorySize,
                         ATT_SMEM_BYTES);
    dim3 ga(NN / 128, HH, BB);
    attn_kernel<<<ga, 256, ATT_SMEM_BYTES>>>();

    ln_attn_kernel<<<RR, 128>>>();

    cudaFuncSetAttribute(gemm_out_kernel,
                         cudaFuncAttributeMaxDynamicSharedMemorySize, G_SMEM);
    dim3 g2(DD / 128, RR / 128);
    gemm_out_kernel<<<g2, 256, G_SMEM>>>(o_b, x, out);
}